// round 1
// baseline (speedup 1.0000x reference)
#include <cuda_runtime.h>
#include <cuda_bf16.h>
#include <math.h>

// Problem constants
#define BB 2
#define SS 2048
#define DD 1024
#define HH 16
#define DK 64
#define MM (BB * SS)   // 4096

// Scratch (device globals: allocation rules forbid cudaMalloc)
__device__ float g_q[MM * DD];
__device__ float g_k[MM * DD];
__device__ float g_v[MM * DD];
__device__ float g_o[MM * DD];

// ---------------------------------------------------------------------------
// GEMM: C[m,n] = sum_k A[m,k] * W[n,k]   (einsum 'md,ed->me')
// 64x64 tile, BK=16, 256 threads, 4x4 microtile.
// Optional fused RoPE epilogue (rope != 0): rotates adjacent column pairs
// within each 64-wide head using cos/sin tables [S, DK/2].
// ---------------------------------------------------------------------------
__global__ __launch_bounds__(256)
void gemm_rope_kernel(const float* __restrict__ A,
                      const float* __restrict__ W,
                      float* __restrict__ C,
                      const float* __restrict__ rc,
                      const float* __restrict__ rs,
                      int M, int N, int K, int rope)
{
    __shared__ float As[16][68];   // [k][m], padded
    __shared__ float Bs[16][68];   // [k][n], padded

    const int tid = threadIdx.x;
    const int tx = tid & 15;
    const int ty = tid >> 4;
    const int m0 = blockIdx.y * 64;
    const int n0 = blockIdx.x * 64;

    // loader mapping: each thread loads one float4 of A and one of W per slab
    const int lm = tid >> 2;          // 0..63
    const int lk = (tid & 3) << 2;    // 0,4,8,12

    float acc[4][4];
#pragma unroll
    for (int i = 0; i < 4; i++)
#pragma unroll
        for (int j = 0; j < 4; j++) acc[i][j] = 0.f;

    const float* Arow = A + (size_t)(m0 + lm) * K + lk;
    const float* Wrow = W + (size_t)(n0 + lm) * K + lk;

    for (int k0 = 0; k0 < K; k0 += 16) {
        float4 av = *(const float4*)(Arow + k0);
        float4 wv = *(const float4*)(Wrow + k0);
        As[lk + 0][lm] = av.x; As[lk + 1][lm] = av.y;
        As[lk + 2][lm] = av.z; As[lk + 3][lm] = av.w;
        Bs[lk + 0][lm] = wv.x; Bs[lk + 1][lm] = wv.y;
        Bs[lk + 2][lm] = wv.z; Bs[lk + 3][lm] = wv.w;
        __syncthreads();

#pragma unroll
        for (int kk = 0; kk < 16; kk++) {
            float4 a4 = *(const float4*)&As[kk][ty << 2];
            float4 b4 = *(const float4*)&Bs[kk][tx << 2];
            float a[4] = {a4.x, a4.y, a4.z, a4.w};
            float b[4] = {b4.x, b4.y, b4.z, b4.w};
#pragma unroll
            for (int i = 0; i < 4; i++)
#pragma unroll
                for (int j = 0; j < 4; j++)
                    acc[i][j] = fmaf(a[i], b[j], acc[i][j]);
        }
        __syncthreads();
    }

    // Epilogue
#pragma unroll
    for (int i = 0; i < 4; i++) {
        const int row = m0 + (ty << 2) + i;
        const int colb = n0 + (tx << 2);
        float* Crow = C + (size_t)row * N + colb;
        if (rope) {
            const int s = row & (SS - 1);   // seq position (M = B*S, S pow2)
#pragma unroll
            for (int pp = 0; pp < 4; pp += 2) {
                const int col = colb + pp;
                const int p = (col & (DK - 1)) >> 1;
                const float c  = rc[s * (DK / 2) + p];
                const float sn = rs[s * (DK / 2) + p];
                const float a0 = acc[i][pp];
                const float a1 = acc[i][pp + 1];
                Crow[pp]     = a0 * c - a1 * sn;
                Crow[pp + 1] = a0 * sn + a1 * c;
            }
        } else {
            float4 v = make_float4(acc[i][0], acc[i][1], acc[i][2], acc[i][3]);
            *(float4*)Crow = v;
        }
    }
}

// ---------------------------------------------------------------------------
// Flash attention (causal). Q tile = 64 rows, KV tiles of 64.
// Logits = (q.k) / DK  (reference applies 1/sqrt(DK) twice); masked -> -1e30.
// Block: 256 threads (16x16), 4x4 microtiles for both QK^T and PV.
// Dynamic smem: QsT[64][68] (dk-major), KsT[64][68] (dk-major),
//               Vs[64][68] (kv-major), PsT[64][68] (kv-major).
// ---------------------------------------------------------------------------
#define LDP 68
__global__ __launch_bounds__(256)
void flash_kernel(const float* __restrict__ Q,
                  const float* __restrict__ Kk,
                  const float* __restrict__ V,
                  float* __restrict__ O)
{
    extern __shared__ float sm[];
    float* QsT = sm;
    float* KsT = sm + 64 * LDP;
    float* Vs  = sm + 2 * 64 * LDP;
    float* PsT = sm + 3 * 64 * LDP;

    const int tid = threadIdx.x;
    const int tx = tid & 15;
    const int ty = tid >> 4;
    const int qtile = blockIdx.x;
    const int bh = blockIdx.y;
    const int b = bh / HH;
    const int h = bh % HH;
    const int q0 = qtile * 64;
    const size_t base = ((size_t)b * SS) * DD + h * DK;

    // Load Q tile, transposed to dk-major
    for (int i = tid; i < 64 * 16; i += 256) {
        const int r = i >> 4;
        const int d4 = (i & 15) << 2;
        const float4 v = *(const float4*)&Q[base + (size_t)(q0 + r) * DD + d4];
        QsT[(d4 + 0) * LDP + r] = v.x;
        QsT[(d4 + 1) * LDP + r] = v.y;
        QsT[(d4 + 2) * LDP + r] = v.z;
        QsT[(d4 + 3) * LDP + r] = v.w;
    }

    float o[4][4];
    float mi[4], li[4];
#pragma unroll
    for (int i = 0; i < 4; i++) {
        mi[i] = -INFINITY;
        li[i] = 0.f;
#pragma unroll
        for (int j = 0; j < 4; j++) o[i][j] = 0.f;
    }

    for (int jt = 0; jt <= qtile; ++jt) {
        const int k0 = jt * 64;
        __syncthreads();   // protect K/V/P smem from previous iteration's readers

        // Load K (transposed, dk-major) and V (kv-major)
        for (int i = tid; i < 64 * 16; i += 256) {
            const int r = i >> 4;
            const int d4 = (i & 15) << 2;
            const float4 kv = *(const float4*)&Kk[base + (size_t)(k0 + r) * DD + d4];
            KsT[(d4 + 0) * LDP + r] = kv.x;
            KsT[(d4 + 1) * LDP + r] = kv.y;
            KsT[(d4 + 2) * LDP + r] = kv.z;
            KsT[(d4 + 3) * LDP + r] = kv.w;
            const float4 vv = *(const float4*)&V[base + (size_t)(k0 + r) * DD + d4];
            *(float4*)&Vs[r * LDP + d4] = vv;
        }
        __syncthreads();

        // S = Q K^T
        float s[4][4];
#pragma unroll
        for (int i = 0; i < 4; i++)
#pragma unroll
            for (int j = 0; j < 4; j++) s[i][j] = 0.f;

#pragma unroll 8
        for (int kk = 0; kk < 64; kk++) {
            float4 q4 = *(const float4*)&QsT[kk * LDP + (ty << 2)];
            float4 k4 = *(const float4*)&KsT[kk * LDP + (tx << 2)];
            float qa[4] = {q4.x, q4.y, q4.z, q4.w};
            float kb[4] = {k4.x, k4.y, k4.z, k4.w};
#pragma unroll
            for (int i = 0; i < 4; i++)
#pragma unroll
                for (int j = 0; j < 4; j++)
                    s[i][j] = fmaf(qa[i], kb[j], s[i][j]);
        }

        const bool diag = (jt == qtile);
        const float inv2 = 1.0f / (float)DK;   // applied twice in reference
#pragma unroll
        for (int i = 0; i < 4; i++) {
            const int qpos = q0 + (ty << 2) + i;
#pragma unroll
            for (int j = 0; j < 4; j++) {
                float sv = s[i][j] * inv2;
                if (diag && (k0 + (tx << 2) + j > qpos)) sv = -1e30f;
                s[i][j] = sv;
            }
        }

        // Online softmax update
#pragma unroll
        for (int i = 0; i < 4; i++) {
            float tmax = fmaxf(fmaxf(s[i][0], s[i][1]), fmaxf(s[i][2], s[i][3]));
#pragma unroll
            for (int off = 8; off > 0; off >>= 1)
                tmax = fmaxf(tmax, __shfl_xor_sync(0xffffffffu, tmax, off, 16));
            const float newm = fmaxf(mi[i], tmax);
            const float alpha = expf(mi[i] - newm);
            float tsum = 0.f;
#pragma unroll
            for (int j = 0; j < 4; j++) {
                const float p = expf(s[i][j] - newm);
                s[i][j] = p;
                tsum += p;
            }
#pragma unroll
            for (int off = 8; off > 0; off >>= 1)
                tsum += __shfl_xor_sync(0xffffffffu, tsum, off, 16);
            li[i] = li[i] * alpha + tsum;
            mi[i] = newm;
#pragma unroll
            for (int j = 0; j < 4; j++) o[i][j] *= alpha;
        }

        // Stash P transposed (kv-major)
#pragma unroll
        for (int i = 0; i < 4; i++)
#pragma unroll
            for (int j = 0; j < 4; j++)
                PsT[((tx << 2) + j) * LDP + (ty << 2) + i] = s[i][j];
        __syncthreads();

        // O += P V
#pragma unroll 8
        for (int kk = 0; kk < 64; kk++) {
            float4 p4 = *(const float4*)&PsT[kk * LDP + (ty << 2)];
            float4 v4 = *(const float4*)&Vs[kk * LDP + (tx << 2)];
            float pa[4] = {p4.x, p4.y, p4.z, p4.w};
            float vb[4] = {v4.x, v4.y, v4.z, v4.w};
#pragma unroll
            for (int i = 0; i < 4; i++)
#pragma unroll
                for (int j = 0; j < 4; j++)
                    o[i][j] = fmaf(pa[i], vb[j], o[i][j]);
        }
    }

    // Finalize
#pragma unroll
    for (int i = 0; i < 4; i++) {
        const float invl = 1.0f / li[i];
        const int r = q0 + (ty << 2) + i;
        float* Orow = O + base + (size_t)r * DD + (tx << 2);
        float4 v = make_float4(o[i][0] * invl, o[i][1] * invl,
                               o[i][2] * invl, o[i][3] * invl);
        *(float4*)Orow = v;
    }
}

// ---------------------------------------------------------------------------
extern "C" void kernel_launch(void* const* d_in, const int* in_sizes, int n_in,
                              void* d_out, int out_size)
{
    const float* x  = (const float*)d_in[0];
    const float* rc = (const float*)d_in[1];
    const float* rs = (const float*)d_in[2];
    // d_in[3] = mask (causal; handled analytically)
    const float* wq = (const float*)d_in[4];
    const float* wk = (const float*)d_in[5];
    const float* wv = (const float*)d_in[6];
    const float* wo = (const float*)d_in[7];
    float* out = (float*)d_out;

    float *q, *k, *v, *o;
    cudaGetSymbolAddress((void**)&q, g_q);
    cudaGetSymbolAddress((void**)&k, g_k);
    cudaGetSymbolAddress((void**)&v, g_v);
    cudaGetSymbolAddress((void**)&o, g_o);

    const int smem_flash = 4 * 64 * LDP * sizeof(float);
    cudaFuncSetAttribute(flash_kernel,
                         cudaFuncAttributeMaxDynamicSharedMemorySize, smem_flash);

    dim3 gg(DD / 64, MM / 64);   // (16, 64)
    gemm_rope_kernel<<<gg, 256>>>(x, wq, q, rc, rs, MM, DD, DD, 1);
    gemm_rope_kernel<<<gg, 256>>>(x, wk, k, rc, rs, MM, DD, DD, 1);
    gemm_rope_kernel<<<gg, 256>>>(x, wv, v, nullptr, nullptr, MM, DD, DD, 0);

    dim3 gf(SS / 64, BB * HH);   // (32, 32)
    flash_kernel<<<gf, 256, smem_flash>>>(q, k, v, o);

    gemm_rope_kernel<<<gg, 256>>>(o, wo, out, nullptr, nullptr, MM, DD, DD, 0);
}

// round 4
// speedup vs baseline: 1.5655x; 1.5655x over previous
#include <cuda_runtime.h>
#include <cuda_bf16.h>
#include <math.h>
#include <cstdint>

// Problem constants
#define BB 2
#define SS 2048
#define DD 1024
#define HH 16
#define DK 64
#define MM (BB * SS)   // 4096

// Scratch (device globals: allocation rules forbid cudaMalloc)
__device__ float g_q[MM * DD];
__device__ float g_k[MM * DD];
__device__ float g_v[MM * DD];
__device__ float g_o[MM * DD];
__device__ __nv_bfloat16 g_xh[MM * DD];
__device__ __nv_bfloat16 g_xl[MM * DD];
__device__ __nv_bfloat16 g_oh[MM * DD];
__device__ __nv_bfloat16 g_ol[MM * DD];
__device__ __nv_bfloat16 g_wh[4][DD * DD];
__device__ __nv_bfloat16 g_wl[4][DD * DD];

// ---------------------------------------------------------------------------
// Helpers (sm_80-baseline PTX only: ldmatrix / mma.sync / cp.async)
// ---------------------------------------------------------------------------
__device__ __forceinline__ uint32_t smem_u32(const void* p) {
    uint32_t a;
    asm("{ .reg .u64 t; cvta.to.shared.u64 t, %1; cvt.u32.u64 %0, t; }" : "=r"(a) : "l"(p));
    return a;
}
__device__ __forceinline__ void cpa16(uint32_t s, const void* g) {
    asm volatile("cp.async.cg.shared.global [%0], [%1], 16;" :: "r"(s), "l"(g));
}
#define CP_COMMIT() asm volatile("cp.async.commit_group;")
#define CP_WAIT(n)  asm volatile("cp.async.wait_group %0;" :: "n"(n))

__device__ __forceinline__ void ldm_x4(uint32_t& r0, uint32_t& r1, uint32_t& r2,
                                       uint32_t& r3, uint32_t addr) {
    asm volatile("ldmatrix.sync.aligned.m8n8.x4.shared.b16 {%0,%1,%2,%3}, [%4];"
                 : "=r"(r0), "=r"(r1), "=r"(r2), "=r"(r3) : "r"(addr));
}
__device__ __forceinline__ void mma_bf16(float* d, const uint32_t* a, const uint32_t* b) {
    asm volatile(
        "mma.sync.aligned.m16n8k16.row.col.f32.bf16.bf16.f32 "
        "{%0,%1,%2,%3}, {%4,%5,%6,%7}, {%8,%9}, {%0,%1,%2,%3};"
        : "+f"(d[0]), "+f"(d[1]), "+f"(d[2]), "+f"(d[3])
        : "r"(a[0]), "r"(a[1]), "r"(a[2]), "r"(a[3]), "r"(b[0]), "r"(b[1]));
}

// ---------------------------------------------------------------------------
// Split fp32 -> (bf16 hi, bf16 residual lo)
// ---------------------------------------------------------------------------
__global__ __launch_bounds__(256)
void split_kernel(const float4* __restrict__ src,
                  __nv_bfloat16* __restrict__ hi,
                  __nv_bfloat16* __restrict__ lo, int n4)
{
    int i = blockIdx.x * 256 + threadIdx.x;
    if (i < n4) {
        float4 s = src[i];
        __nv_bfloat16 h0 = __float2bfloat16(s.x);
        __nv_bfloat16 h1 = __float2bfloat16(s.y);
        __nv_bfloat16 h2 = __float2bfloat16(s.z);
        __nv_bfloat16 h3 = __float2bfloat16(s.w);
        __nv_bfloat162* H = (__nv_bfloat162*)(hi + 4 * (size_t)i);
        __nv_bfloat162* L = (__nv_bfloat162*)(lo + 4 * (size_t)i);
        H[0] = __nv_bfloat162{h0, h1};
        H[1] = __nv_bfloat162{h2, h3};
        L[0] = __nv_bfloat162{__float2bfloat16(s.x - __bfloat162float(h0)),
                              __float2bfloat16(s.y - __bfloat162float(h1))};
        L[1] = __nv_bfloat162{__float2bfloat16(s.z - __bfloat162float(h2)),
                              __float2bfloat16(s.w - __bfloat162float(h3))};
    }
}

// ---------------------------------------------------------------------------
// mma.sync bf16x3 GEMM: C[m,n] = sum_k A[m,k] * W[n,k]  (both K-major)
// 128x128 tile, BK=32, 8 warps (4 m x 2 n), 3-stage cp.async pipeline.
// Smem row per tile row: 128B = [hi k0..31 (64B) | lo k0..31 (64B)], SW128
// swizzled per 16B chunk: chunk' = chunk ^ (row & 7) -> conflict-free ldmatrix.
// Optional fused RoPE epilogue (z < nz_rope).
// grid: (N/128, M/128, nmat); block: 256 threads.
// ---------------------------------------------------------------------------
struct GemmArgs {
    const __nv_bfloat16* Ah; const __nv_bfloat16* Al;
    const __nv_bfloat16* Wh[3]; const __nv_bfloat16* Wl[3];
    float* C[3];
    const float* rc; const float* rs;
    int nz_rope;
};

#define TILE_BYTES 16384            // 128 rows x 128B
#define STAGE_BYTES (2 * TILE_BYTES)
#define GEMM_SMEM (3 * STAGE_BYTES) // 98304

__global__ __launch_bounds__(256)
void gemm_mma_kernel(GemmArgs p)
{
    extern __shared__ char smem[];
    const uint32_t sb = smem_u32(smem);
    const int tid = threadIdx.x;
    const int lane = tid & 31, wid = tid >> 5;
    const int warp_m = wid & 3, warp_n = wid >> 2;
    const int z = blockIdx.z;
    const int n0 = blockIdx.x * 128, m0 = blockIdx.y * 128;

    const __nv_bfloat16* srcs[4] = {
        p.Ah + (size_t)m0 * DD, p.Al + (size_t)m0 * DD,
        p.Wh[z] + (size_t)n0 * DD, p.Wl[z] + (size_t)n0 * DD };

    // loader: chunk c (32 k-floats) into stage st
    auto load_chunk = [&](int c, int st) {
#pragma unroll
        for (int i = 0; i < 8; i++) {
            const int s = tid + i * 256;       // 0..2047
            const int tile = s >> 10;          // 0: A, 1: W
            const int t = s & 1023;
            const int row = t >> 3;
            const int ch = t & 7;              // 0-3 hi, 4-7 lo
            const int hl = ch >> 2, col8 = ch & 3;
            const __nv_bfloat16* g = srcs[tile * 2 + hl] +
                (size_t)row * DD + c * 32 + col8 * 8;
            const uint32_t dst = sb + st * STAGE_BYTES + tile * TILE_BYTES +
                row * 128 + ((ch ^ (row & 7)) << 4);
            cpa16(dst, g);
        }
    };

    float acc[2][8][4];
#pragma unroll
    for (int m = 0; m < 2; m++)
#pragma unroll
        for (int n = 0; n < 8; n++)
#pragma unroll
            for (int j = 0; j < 4; j++) acc[m][n][j] = 0.f;

    load_chunk(0, 0); CP_COMMIT();
    load_chunk(1, 1); CP_COMMIT();

    const int sub = lane >> 3, r8 = lane & 7;

    for (int c = 0; c < 32; c++) {
        __syncthreads();                    // stage (c+2)%3 free to overwrite
        if (c + 2 < 32) load_chunk(c + 2, (c + 2) % 3);
        CP_COMMIT();
        CP_WAIT(2);                         // chunk c resident
        __syncthreads();

        const uint32_t Ab = sb + (c % 3) * STAGE_BYTES;
        const uint32_t Wb = Ab + TILE_BYTES;

#pragma unroll
        for (int ka = 0; ka < 2; ka++) {
            // A fragments: [matom][hl][4]
            uint32_t afr[2][2][4];
#pragma unroll
            for (int m = 0; m < 2; m++)
#pragma unroll
                for (int hl = 0; hl < 2; hl++) {
                    const int row = warp_m * 32 + m * 16 + (sub & 1) * 8 + r8;
                    const int ch = hl * 4 + ka * 2 + (sub >> 1);
                    const uint32_t addr = Ab + row * 128 + ((ch ^ (row & 7)) << 4);
                    ldm_x4(afr[m][hl][0], afr[m][hl][1], afr[m][hl][2], afr[m][hl][3], addr);
                }
            // B fragments: [hl][natom][2]
            uint32_t bfr[2][8][2];
#pragma unroll
            for (int np = 0; np < 4; np++)
#pragma unroll
                for (int hl = 0; hl < 2; hl++) {
                    const int row = warp_n * 64 + np * 16 + (sub >> 1) * 8 + r8;
                    const int ch = hl * 4 + ka * 2 + (sub & 1);
                    const uint32_t addr = Wb + row * 128 + ((ch ^ (row & 7)) << 4);
                    uint32_t r0, r1, r2, r3;
                    ldm_x4(r0, r1, r2, r3, addr);
                    bfr[hl][np * 2][0] = r0;     bfr[hl][np * 2][1] = r1;
                    bfr[hl][np * 2 + 1][0] = r2; bfr[hl][np * 2 + 1][1] = r3;
                }
#pragma unroll
            for (int m = 0; m < 2; m++)
#pragma unroll
                for (int n = 0; n < 8; n++) {
                    mma_bf16(acc[m][n], afr[m][0], bfr[0][n]);  // hi*hi
                    mma_bf16(acc[m][n], afr[m][0], bfr[1][n]);  // hi*lo
                    mma_bf16(acc[m][n], afr[m][1], bfr[0][n]);  // lo*hi
                }
        }
    }

    // Epilogue (optional RoPE); C-frag col pair (lane&3)*2 is a rotation pair.
    float* C = p.C[z];
    const bool rope = (z < p.nz_rope);
    const int lane4 = lane >> 2, lanem = lane & 3;
#pragma unroll
    for (int m = 0; m < 2; m++)
#pragma unroll
        for (int n = 0; n < 8; n++) {
            const int col = n0 + warp_n * 64 + n * 8 + lanem * 2;
#pragma unroll
            for (int half = 0; half < 2; half++) {
                const int row = m0 + warp_m * 32 + m * 16 + lane4 + half * 8;
                float a0 = acc[m][n][half * 2 + 0];
                float a1 = acc[m][n][half * 2 + 1];
                if (rope) {
                    const int s = row & (SS - 1);
                    const int pi = (col & (DK - 1)) >> 1;
                    const float cc = p.rc[s * (DK / 2) + pi];
                    const float sn = p.rs[s * (DK / 2) + pi];
                    const float t0 = a0 * cc - a1 * sn;
                    const float t1 = a0 * sn + a1 * cc;
                    a0 = t0; a1 = t1;
                }
                *(float2*)(C + (size_t)row * DD + col) = make_float2(a0, a1);
            }
        }
}

// ---------------------------------------------------------------------------
// Flash attention (causal) — SIMT version (proven in R1).
// ---------------------------------------------------------------------------
#define LDP 68
__global__ __launch_bounds__(256)
void flash_kernel(const float* __restrict__ Q,
                  const float* __restrict__ Kk,
                  const float* __restrict__ V,
                  float* __restrict__ O)
{
    extern __shared__ float sm[];
    float* QsT = sm;
    float* KsT = sm + 64 * LDP;
    float* Vs  = sm + 2 * 64 * LDP;
    float* PsT = sm + 3 * 64 * LDP;

    const int tid = threadIdx.x;
    const int tx = tid & 15;
    const int ty = tid >> 4;
    const int qtile = blockIdx.x;
    const int bh = blockIdx.y;
    const int b = bh / HH;
    const int h = bh % HH;
    const int q0 = qtile * 64;
    const size_t base = ((size_t)b * SS) * DD + h * DK;

    for (int i = tid; i < 64 * 16; i += 256) {
        const int r = i >> 4;
        const int d4 = (i & 15) << 2;
        const float4 v = *(const float4*)&Q[base + (size_t)(q0 + r) * DD + d4];
        QsT[(d4 + 0) * LDP + r] = v.x;
        QsT[(d4 + 1) * LDP + r] = v.y;
        QsT[(d4 + 2) * LDP + r] = v.z;
        QsT[(d4 + 3) * LDP + r] = v.w;
    }

    float o[4][4];
    float mi[4], li[4];
#pragma unroll
    for (int i = 0; i < 4; i++) {
        mi[i] = -INFINITY;
        li[i] = 0.f;
#pragma unroll
        for (int j = 0; j < 4; j++) o[i][j] = 0.f;
    }

    for (int jt = 0; jt <= qtile; ++jt) {
        const int k0 = jt * 64;
        __syncthreads();

        for (int i = tid; i < 64 * 16; i += 256) {
            const int r = i >> 4;
            const int d4 = (i & 15) << 2;
            const float4 kv = *(const float4*)&Kk[base + (size_t)(k0 + r) * DD + d4];
            KsT[(d4 + 0) * LDP + r] = kv.x;
            KsT[(d4 + 1) * LDP + r] = kv.y;
            KsT[(d4 + 2) * LDP + r] = kv.z;
            KsT[(d4 + 3) * LDP + r] = kv.w;
            const float4 vv = *(const float4*)&V[base + (size_t)(k0 + r) * DD + d4];
            *(float4*)&Vs[r * LDP + d4] = vv;
        }
        __syncthreads();

        float s[4][4];
#pragma unroll
        for (int i = 0; i < 4; i++)
#pragma unroll
            for (int j = 0; j < 4; j++) s[i][j] = 0.f;

#pragma unroll 8
        for (int kk = 0; kk < 64; kk++) {
            float4 q4 = *(const float4*)&QsT[kk * LDP + (ty << 2)];
            float4 k4 = *(const float4*)&KsT[kk * LDP + (tx << 2)];
            float qa[4] = {q4.x, q4.y, q4.z, q4.w};
            float kb[4] = {k4.x, k4.y, k4.z, k4.w};
#pragma unroll
            for (int i = 0; i < 4; i++)
#pragma unroll
                for (int j = 0; j < 4; j++)
                    s[i][j] = fmaf(qa[i], kb[j], s[i][j]);
        }

        const bool diag = (jt == qtile);
        const float inv2 = 1.0f / (float)DK;
#pragma unroll
        for (int i = 0; i < 4; i++) {
            const int qpos = q0 + (ty << 2) + i;
#pragma unroll
            for (int j = 0; j < 4; j++) {
                float sv = s[i][j] * inv2;
                if (diag && (k0 + (tx << 2) + j > qpos)) sv = -1e30f;
                s[i][j] = sv;
            }
        }

#pragma unroll
        for (int i = 0; i < 4; i++) {
            float tmax = fmaxf(fmaxf(s[i][0], s[i][1]), fmaxf(s[i][2], s[i][3]));
#pragma unroll
            for (int off = 8; off > 0; off >>= 1)
                tmax = fmaxf(tmax, __shfl_xor_sync(0xffffffffu, tmax, off, 16));
            const float newm = fmaxf(mi[i], tmax);
            const float alpha = expf(mi[i] - newm);
            float tsum = 0.f;
#pragma unroll
            for (int j = 0; j < 4; j++) {
                const float p = expf(s[i][j] - newm);
                s[i][j] = p;
                tsum += p;
            }
#pragma unroll
            for (int off = 8; off > 0; off >>= 1)
                tsum += __shfl_xor_sync(0xffffffffu, tsum, off, 16);
            li[i] = li[i] * alpha + tsum;
            mi[i] = newm;
#pragma unroll
            for (int j = 0; j < 4; j++) o[i][j] *= alpha;
        }

#pragma unroll
        for (int i = 0; i < 4; i++)
#pragma unroll
            for (int j = 0; j < 4; j++)
                PsT[((tx << 2) + j) * LDP + (ty << 2) + i] = s[i][j];
        __syncthreads();

#pragma unroll 8
        for (int kk = 0; kk < 64; kk++) {
            float4 p4 = *(const float4*)&PsT[kk * LDP + (ty << 2)];
            float4 v4 = *(const float4*)&Vs[kk * LDP + (tx << 2)];
            float pa[4] = {p4.x, p4.y, p4.z, p4.w};
            float vb[4] = {v4.x, v4.y, v4.z, v4.w};
#pragma unroll
            for (int i = 0; i < 4; i++)
#pragma unroll
                for (int j = 0; j < 4; j++)
                    o[i][j] = fmaf(pa[i], vb[j], o[i][j]);
        }
    }

#pragma unroll
    for (int i = 0; i < 4; i++) {
        const float invl = 1.0f / li[i];
        const int r = q0 + (ty << 2) + i;
        float* Orow = O + base + (size_t)r * DD + (tx << 2);
        float4 v = make_float4(o[i][0] * invl, o[i][1] * invl,
                               o[i][2] * invl, o[i][3] * invl);
        *(float4*)Orow = v;
    }
}

// ---------------------------------------------------------------------------
extern "C" void kernel_launch(void* const* d_in, const int* in_sizes, int n_in,
                              void* d_out, int out_size)
{
    const float* x  = (const float*)d_in[0];
    const float* rc = (const float*)d_in[1];
    const float* rs = (const float*)d_in[2];
    // d_in[3] = mask (causal; handled analytically)
    const float* w_in[4] = {(const float*)d_in[4], (const float*)d_in[5],
                            (const float*)d_in[6], (const float*)d_in[7]};
    float* out = (float*)d_out;

    float *q, *k, *v, *o;
    __nv_bfloat16 *xh, *xl, *oh, *ol, *wh, *wl;
    cudaGetSymbolAddress((void**)&q,  g_q);
    cudaGetSymbolAddress((void**)&k,  g_k);
    cudaGetSymbolAddress((void**)&v,  g_v);
    cudaGetSymbolAddress((void**)&o,  g_o);
    cudaGetSymbolAddress((void**)&xh, g_xh);
    cudaGetSymbolAddress((void**)&xl, g_xl);
    cudaGetSymbolAddress((void**)&oh, g_oh);
    cudaGetSymbolAddress((void**)&ol, g_ol);
    cudaGetSymbolAddress((void**)&wh, g_wh);
    cudaGetSymbolAddress((void**)&wl, g_wl);

    cudaFuncSetAttribute(gemm_mma_kernel,
                         cudaFuncAttributeMaxDynamicSharedMemorySize, GEMM_SMEM);
    cudaFuncSetAttribute(flash_kernel,
                         cudaFuncAttributeMaxDynamicSharedMemorySize,
                         4 * 64 * LDP * (int)sizeof(float));

    // 1) splits: x and the four weight matrices
    split_kernel<<<(MM * DD / 4 + 255) / 256, 256>>>((const float4*)x, xh, xl, MM * DD / 4);
    for (int i = 0; i < 4; i++) {
        split_kernel<<<(DD * DD / 4 + 255) / 256, 256>>>(
            (const float4*)w_in[i], wh + (size_t)i * DD * DD,
            wl + (size_t)i * DD * DD, DD * DD / 4);
    }

    // 2) fused QKV projections (+RoPE on Q,K)
    GemmArgs aq{};
    aq.Ah = xh; aq.Al = xl;
    aq.Wh[0] = wh;                   aq.Wl[0] = wl;
    aq.Wh[1] = wh + (size_t)DD*DD;   aq.Wl[1] = wl + (size_t)DD*DD;
    aq.Wh[2] = wh + (size_t)2*DD*DD; aq.Wl[2] = wl + (size_t)2*DD*DD;
    aq.C[0] = q; aq.C[1] = k; aq.C[2] = v;
    aq.rc = rc; aq.rs = rs; aq.nz_rope = 2;
    gemm_mma_kernel<<<dim3(DD / 128, MM / 128, 3), 256, GEMM_SMEM>>>(aq);

    // 3) attention
    const int smem_flash = 4 * 64 * LDP * (int)sizeof(float);
    flash_kernel<<<dim3(SS / 64, BB * HH), 256, smem_flash>>>(q, k, v, o);

    // 4) split attention output, then output projection
    split_kernel<<<(MM * DD / 4 + 255) / 256, 256>>>((const float4*)o, oh, ol, MM * DD / 4);

    GemmArgs ao{};
    ao.Ah = oh; ao.Al = ol;
    ao.Wh[0] = wh + (size_t)3*DD*DD; ao.Wl[0] = wl + (size_t)3*DD*DD;
    ao.Wh[1] = ao.Wh[0]; ao.Wh[2] = ao.Wh[0];
    ao.Wl[1] = ao.Wl[0]; ao.Wl[2] = ao.Wl[0];
    ao.C[0] = out; ao.C[1] = out; ao.C[2] = out;
    ao.rc = rc; ao.rs = rs; ao.nz_rope = 0;
    gemm_mma_kernel<<<dim3(DD / 128, MM / 128, 1), 256, GEMM_SMEM>>>(ao);
}

// round 5
// speedup vs baseline: 2.9187x; 1.8645x over previous
#include <cuda_runtime.h>
#include <cuda_bf16.h>
#include <math.h>
#include <cstdint>

// Problem constants
#define BB 2
#define SS 2048
#define DD 1024
#define HH 16
#define DK 64
#define MM (BB * SS)   // 4096

// Scratch (device globals: allocation rules forbid cudaMalloc)
__device__ __nv_bfloat16 g_xh[MM * DD];
__device__ __nv_bfloat16 g_xl[MM * DD];
__device__ __nv_bfloat16 g_qh[MM * DD];
__device__ __nv_bfloat16 g_ql[MM * DD];
__device__ __nv_bfloat16 g_kh[MM * DD];
__device__ __nv_bfloat16 g_kl[MM * DD];
__device__ __nv_bfloat16 g_vh[MM * DD];
__device__ __nv_bfloat16 g_vl[MM * DD];
__device__ __nv_bfloat16 g_oh[MM * DD];
__device__ __nv_bfloat16 g_ol[MM * DD];
__device__ __nv_bfloat16 g_wh[4][DD * DD];
__device__ __nv_bfloat16 g_wl[4][DD * DD];

// ---------------------------------------------------------------------------
// Helpers (sm_80-baseline PTX: ldmatrix / mma.sync / cp.async)
// ---------------------------------------------------------------------------
__device__ __forceinline__ uint32_t smem_u32(const void* p) {
    uint32_t a;
    asm("{ .reg .u64 t; cvta.to.shared.u64 t, %1; cvt.u32.u64 %0, t; }" : "=r"(a) : "l"(p));
    return a;
}
__device__ __forceinline__ void cpa16(uint32_t s, const void* g) {
    asm volatile("cp.async.cg.shared.global [%0], [%1], 16;" :: "r"(s), "l"(g));
}
#define CP_COMMIT() asm volatile("cp.async.commit_group;")
#define CP_WAIT(n)  asm volatile("cp.async.wait_group %0;" :: "n"(n))

__device__ __forceinline__ void ldm_x4(uint32_t& r0, uint32_t& r1, uint32_t& r2,
                                       uint32_t& r3, uint32_t addr) {
    asm volatile("ldmatrix.sync.aligned.m8n8.x4.shared.b16 {%0,%1,%2,%3}, [%4];"
                 : "=r"(r0), "=r"(r1), "=r"(r2), "=r"(r3) : "r"(addr));
}
__device__ __forceinline__ void ldm_x4t(uint32_t& r0, uint32_t& r1, uint32_t& r2,
                                        uint32_t& r3, uint32_t addr) {
    asm volatile("ldmatrix.sync.aligned.m8n8.x4.trans.shared.b16 {%0,%1,%2,%3}, [%4];"
                 : "=r"(r0), "=r"(r1), "=r"(r2), "=r"(r3) : "r"(addr));
}
__device__ __forceinline__ void mma_bf16(float* d, const uint32_t* a, const uint32_t* b) {
    asm volatile(
        "mma.sync.aligned.m16n8k16.row.col.f32.bf16.bf16.f32 "
        "{%0,%1,%2,%3}, {%4,%5,%6,%7}, {%8,%9}, {%0,%1,%2,%3};"
        : "+f"(d[0]), "+f"(d[1]), "+f"(d[2]), "+f"(d[3])
        : "r"(a[0]), "r"(a[1]), "r"(a[2]), "r"(a[3]), "r"(b[0]), "r"(b[1]));
}
__device__ __forceinline__ float ex2f(float x) {
    float r;
    asm("ex2.approx.f32 %0, %1;" : "=f"(r) : "f"(x));
    return r;
}
__device__ __forceinline__ uint32_t packbf(float a, float b) {
    __nv_bfloat162 t = __floats2bfloat162_rn(a, b);
    return *(uint32_t*)&t;
}

// ---------------------------------------------------------------------------
// Split fp32 -> (bf16 hi, bf16 residual lo)
// ---------------------------------------------------------------------------
__global__ __launch_bounds__(256)
void split_kernel(const float4* __restrict__ src,
                  __nv_bfloat16* __restrict__ hi,
                  __nv_bfloat16* __restrict__ lo, int n4)
{
    int i = blockIdx.x * 256 + threadIdx.x;
    if (i < n4) {
        float4 s = src[i];
        __nv_bfloat16 h0 = __float2bfloat16(s.x);
        __nv_bfloat16 h1 = __float2bfloat16(s.y);
        __nv_bfloat16 h2 = __float2bfloat16(s.z);
        __nv_bfloat16 h3 = __float2bfloat16(s.w);
        __nv_bfloat162* H = (__nv_bfloat162*)(hi + 4 * (size_t)i);
        __nv_bfloat162* L = (__nv_bfloat162*)(lo + 4 * (size_t)i);
        H[0] = __nv_bfloat162{h0, h1};
        H[1] = __nv_bfloat162{h2, h3};
        L[0] = __nv_bfloat162{__float2bfloat16(s.x - __bfloat162float(h0)),
                              __float2bfloat16(s.y - __bfloat162float(h1))};
        L[1] = __nv_bfloat162{__float2bfloat16(s.z - __bfloat162float(h2)),
                              __float2bfloat16(s.w - __bfloat162float(h3))};
    }
}

// ---------------------------------------------------------------------------
// mma.sync bf16x3 GEMM: C[m,n] = sum_k A[m,k] * W[n,k]  (both K-major)
// 128x128 tile, BK=32, 8 warps (4 m x 2 n), 3-stage cp.async pipeline.
// Epilogue: optional RoPE; output either fp32 (Cf) or bf16 hi/lo (Ch/Cl).
// ---------------------------------------------------------------------------
struct GemmArgs {
    const __nv_bfloat16* Ah; const __nv_bfloat16* Al;
    const __nv_bfloat16* Wh[3]; const __nv_bfloat16* Wl[3];
    __nv_bfloat16* Ch[3]; __nv_bfloat16* Cl[3];
    float* Cf;
    const float* rc; const float* rs;
    int nz_rope; int out_bf16;
};

#define TILE_BYTES 16384            // 128 rows x 128B
#define STAGE_BYTES (2 * TILE_BYTES)
#define GEMM_SMEM (3 * STAGE_BYTES) // 98304

__global__ __launch_bounds__(256)
void gemm_mma_kernel(GemmArgs p)
{
    extern __shared__ char smem[];
    const uint32_t sb = smem_u32(smem);
    const int tid = threadIdx.x;
    const int lane = tid & 31, wid = tid >> 5;
    const int warp_m = wid & 3, warp_n = wid >> 2;
    const int z = blockIdx.z;
    const int n0 = blockIdx.x * 128, m0 = blockIdx.y * 128;

    const __nv_bfloat16* srcs[4] = {
        p.Ah + (size_t)m0 * DD, p.Al + (size_t)m0 * DD,
        p.Wh[z] + (size_t)n0 * DD, p.Wl[z] + (size_t)n0 * DD };

    auto load_chunk = [&](int c, int st) {
#pragma unroll
        for (int i = 0; i < 8; i++) {
            const int s = tid + i * 256;
            const int tile = s >> 10;
            const int t = s & 1023;
            const int row = t >> 3;
            const int ch = t & 7;
            const int hl = ch >> 2, col8 = ch & 3;
            const __nv_bfloat16* g = srcs[tile * 2 + hl] +
                (size_t)row * DD + c * 32 + col8 * 8;
            const uint32_t dst = sb + st * STAGE_BYTES + tile * TILE_BYTES +
                row * 128 + ((ch ^ (row & 7)) << 4);
            cpa16(dst, g);
        }
    };

    float acc[2][8][4];
#pragma unroll
    for (int m = 0; m < 2; m++)
#pragma unroll
        for (int n = 0; n < 8; n++)
#pragma unroll
            for (int j = 0; j < 4; j++) acc[m][n][j] = 0.f;

    load_chunk(0, 0); CP_COMMIT();
    load_chunk(1, 1); CP_COMMIT();

    const int sub = lane >> 3, r8 = lane & 7;

    for (int c = 0; c < 32; c++) {
        __syncthreads();
        if (c + 2 < 32) load_chunk(c + 2, (c + 2) % 3);
        CP_COMMIT();
        CP_WAIT(2);
        __syncthreads();

        const uint32_t Ab = sb + (c % 3) * STAGE_BYTES;
        const uint32_t Wb = Ab + TILE_BYTES;

#pragma unroll
        for (int ka = 0; ka < 2; ka++) {
            uint32_t afr[2][2][4];
#pragma unroll
            for (int m = 0; m < 2; m++)
#pragma unroll
                for (int hl = 0; hl < 2; hl++) {
                    const int row = warp_m * 32 + m * 16 + (sub & 1) * 8 + r8;
                    const int ch = hl * 4 + ka * 2 + (sub >> 1);
                    const uint32_t addr = Ab + row * 128 + ((ch ^ (row & 7)) << 4);
                    ldm_x4(afr[m][hl][0], afr[m][hl][1], afr[m][hl][2], afr[m][hl][3], addr);
                }
            uint32_t bfr[2][8][2];
#pragma unroll
            for (int np = 0; np < 4; np++)
#pragma unroll
                for (int hl = 0; hl < 2; hl++) {
                    const int row = warp_n * 64 + np * 16 + (sub >> 1) * 8 + r8;
                    const int ch = hl * 4 + ka * 2 + (sub & 1);
                    const uint32_t addr = Wb + row * 128 + ((ch ^ (row & 7)) << 4);
                    uint32_t r0, r1, r2, r3;
                    ldm_x4(r0, r1, r2, r3, addr);
                    bfr[hl][np * 2][0] = r0;     bfr[hl][np * 2][1] = r1;
                    bfr[hl][np * 2 + 1][0] = r2; bfr[hl][np * 2 + 1][1] = r3;
                }
#pragma unroll
            for (int m = 0; m < 2; m++)
#pragma unroll
                for (int n = 0; n < 8; n++) {
                    mma_bf16(acc[m][n], afr[m][0], bfr[0][n]);
                    mma_bf16(acc[m][n], afr[m][0], bfr[1][n]);
                    mma_bf16(acc[m][n], afr[m][1], bfr[0][n]);
                }
        }
    }

    const bool rope = (z < p.nz_rope);
    const int lane4 = lane >> 2, lanem = lane & 3;
#pragma unroll
    for (int m = 0; m < 2; m++)
#pragma unroll
        for (int n = 0; n < 8; n++) {
            const int col = n0 + warp_n * 64 + n * 8 + lanem * 2;
#pragma unroll
            for (int half = 0; half < 2; half++) {
                const int row = m0 + warp_m * 32 + m * 16 + lane4 + half * 8;
                float a0 = acc[m][n][half * 2 + 0];
                float a1 = acc[m][n][half * 2 + 1];
                if (rope) {
                    const int s = row & (SS - 1);
                    const int pi = (col & (DK - 1)) >> 1;
                    const float cc = p.rc[s * (DK / 2) + pi];
                    const float sn = p.rs[s * (DK / 2) + pi];
                    const float t0 = a0 * cc - a1 * sn;
                    const float t1 = a0 * sn + a1 * cc;
                    a0 = t0; a1 = t1;
                }
                if (p.out_bf16) {
                    __nv_bfloat162 h = __floats2bfloat162_rn(a0, a1);
                    __nv_bfloat162 l = __floats2bfloat162_rn(
                        a0 - __bfloat162float(h.x), a1 - __bfloat162float(h.y));
                    *(__nv_bfloat162*)(p.Ch[z] + (size_t)row * DD + col) = h;
                    *(__nv_bfloat162*)(p.Cl[z] + (size_t)row * DD + col) = l;
                } else {
                    *(float2*)(p.Cf + (size_t)row * DD + col) = make_float2(a0, a1);
                }
            }
        }
}

// ---------------------------------------------------------------------------
// Tensor-core flash attention (causal), bf16 with hi/lo compensation.
// Q tile 128 rows, KV steps of 64, 8 warps (warp = 16 q-rows), 256 threads.
// logits2 = (q.k) * log2(e)/64; softmax in fp32; P,V hi/lo 3-term PV.
// Smem: Qh/Ql [128][64] + 2 stages of {Kh,Kl,Vh,Vl}[64][64], 128B swizzled rows.
// ---------------------------------------------------------------------------
#define FQ_BYTES 16384              // 128 rows * 128B
#define FKV_TILE 8192               // 64 rows * 128B
#define FSTAGE (4 * FKV_TILE)       // 32768
#define FLASH_SMEM (2 * FQ_BYTES + 2 * FSTAGE)   // 98304

__global__ __launch_bounds__(256)
void flash_tc_kernel(const __nv_bfloat16* __restrict__ qh,
                     const __nv_bfloat16* __restrict__ ql,
                     const __nv_bfloat16* __restrict__ kh,
                     const __nv_bfloat16* __restrict__ kl,
                     const __nv_bfloat16* __restrict__ vh,
                     const __nv_bfloat16* __restrict__ vl,
                     __nv_bfloat16* __restrict__ oh,
                     __nv_bfloat16* __restrict__ ol)
{
    extern __shared__ char smem[];
    const uint32_t sb = smem_u32(smem);
    const int tid = threadIdx.x;
    const int lane = tid & 31, warp = tid >> 5;
    const int sub = lane >> 3, r8 = lane & 7;
    const int qtile = (int)gridDim.x - 1 - (int)blockIdx.x;   // heavy tiles first
    const int bh = blockIdx.y;
    const int b = bh / HH, h = bh % HH;
    const int q0 = qtile * 128;
    const int njt = 2 * qtile + 2;
    const size_t gbase = (size_t)b * SS * DD + h * DK;

    const __nv_bfloat16* qsrc[2] = {qh + gbase, ql + gbase};
    const __nv_bfloat16* kvsrc[4] = {kh + gbase, kl + gbase, vh + gbase, vl + gbase};

    // ---- load Q tile (both components) ----
#pragma unroll
    for (int i = 0; i < 8; i++) {
        const int s = tid + i * 256;         // 0..2047
        const int tile = s >> 10;            // 0: Qh, 1: Ql
        const int t = s & 1023;
        const int row = t >> 3, ch = t & 7;
        cpa16(sb + tile * FQ_BYTES + row * 128 + ((ch ^ (row & 7)) << 4),
              qsrc[tile] + (size_t)(q0 + row) * DD + ch * 8);
    }
    // ---- load KV stage 0 ----
    auto load_kv = [&](int jt, int st) {
        const int k0 = jt * 64;
#pragma unroll
        for (int i = 0; i < 8; i++) {
            const int s = tid + i * 256;     // 0..2047
            const int tile = s >> 9;         // Kh,Kl,Vh,Vl
            const int t = s & 511;
            const int row = t >> 3, ch = t & 7;
            cpa16(sb + 2 * FQ_BYTES + st * FSTAGE + tile * FKV_TILE +
                      row * 128 + ((ch ^ (row & 7)) << 4),
                  kvsrc[tile] + (size_t)(k0 + row) * DD + ch * 8);
        }
    };
    load_kv(0, 0);
    CP_COMMIT();
    CP_WAIT(0);
    __syncthreads();

    // ---- Q fragments register-resident: [katom][hl][4] ----
    uint32_t qfr[4][2][4];
#pragma unroll
    for (int ka = 0; ka < 4; ka++)
#pragma unroll
        for (int hl = 0; hl < 2; hl++) {
            const int row = warp * 16 + (sub & 1) * 8 + r8;
            const int ch = ka * 2 + (sub >> 1);
            ldm_x4(qfr[ka][hl][0], qfr[ka][hl][1], qfr[ka][hl][2], qfr[ka][hl][3],
                   sb + hl * FQ_BYTES + row * 128 + ((ch ^ (row & 7)) << 4));
        }

    float oacc[8][4];
#pragma unroll
    for (int n = 0; n < 8; n++)
#pragma unroll
        for (int j = 0; j < 4; j++) oacc[n][j] = 0.f;
    float mi[2] = {-INFINITY, -INFINITY};
    float li[2] = {0.f, 0.f};

    const float C2 = 1.4426950408889634f / 64.0f;   // log2(e)/64
    const int qrow0 = q0 + warp * 16 + (lane >> 2);

    for (int jt = 0; jt < njt; jt++) {
        const int buf = jt & 1;
        const int k0 = jt * 64;
        __syncthreads();                     // everyone done with buffer 1-buf
        if (jt + 1 < njt) { load_kv(jt + 1, 1 - buf); CP_COMMIT(); CP_WAIT(1); }
        else             { CP_WAIT(0); }
        __syncthreads();

        const uint32_t Kb = sb + 2 * FQ_BYTES + buf * FSTAGE;
        const uint32_t Vb = Kb + 2 * FKV_TILE;

        // ---- S = Q K^T (3-term) ----
        float s[8][4];
#pragma unroll
        for (int n = 0; n < 8; n++)
#pragma unroll
            for (int j = 0; j < 4; j++) s[n][j] = 0.f;

#pragma unroll
        for (int ka = 0; ka < 4; ka++) {
            uint32_t bfr[2][8][2];
#pragma unroll
            for (int np = 0; np < 4; np++)
#pragma unroll
                for (int hl = 0; hl < 2; hl++) {
                    const int row = np * 16 + (sub >> 1) * 8 + r8;
                    const int ch = ka * 2 + (sub & 1);
                    uint32_t r0, r1, r2, r3;
                    ldm_x4(r0, r1, r2, r3,
                           Kb + hl * FKV_TILE + row * 128 + ((ch ^ (row & 7)) << 4));
                    bfr[hl][np * 2][0] = r0;     bfr[hl][np * 2][1] = r1;
                    bfr[hl][np * 2 + 1][0] = r2; bfr[hl][np * 2 + 1][1] = r3;
                }
#pragma unroll
            for (int n = 0; n < 8; n++) {
                mma_bf16(s[n], qfr[ka][0], bfr[0][n]);
                mma_bf16(s[n], qfr[ka][0], bfr[1][n]);
                mma_bf16(s[n], qfr[ka][1], bfr[0][n]);
            }
        }

        // ---- scale + mask ----
        const bool need_mask = (k0 + 64 > qrow0);   // conservative per-lane
#pragma unroll
        for (int n = 0; n < 8; n++) {
            const int col = k0 + n * 8 + (lane & 3) * 2;
#pragma unroll
            for (int j = 0; j < 4; j++) {
                float v = s[n][j] * C2;
                if (need_mask) {
                    const int kv = col + (j & 1);
                    const int qr = qrow0 + (j >> 1) * 8;
                    if (kv > qr) v = -1e30f;
                }
                s[n][j] = v;
            }
        }

        // ---- online softmax ----
        float mx0 = s[0][0], mx1 = s[0][2];
#pragma unroll
        for (int n = 0; n < 8; n++) {
            mx0 = fmaxf(mx0, fmaxf(s[n][0], s[n][1]));
            mx1 = fmaxf(mx1, fmaxf(s[n][2], s[n][3]));
        }
        mx0 = fmaxf(mx0, __shfl_xor_sync(0xffffffffu, mx0, 1));
        mx0 = fmaxf(mx0, __shfl_xor_sync(0xffffffffu, mx0, 2));
        mx1 = fmaxf(mx1, __shfl_xor_sync(0xffffffffu, mx1, 1));
        mx1 = fmaxf(mx1, __shfl_xor_sync(0xffffffffu, mx1, 2));
        const float nm0 = fmaxf(mi[0], mx0), nm1 = fmaxf(mi[1], mx1);
        const float al0 = ex2f(mi[0] - nm0), al1 = ex2f(mi[1] - nm1);
        mi[0] = nm0; mi[1] = nm1;

        float sum0 = 0.f, sum1 = 0.f;
#pragma unroll
        for (int n = 0; n < 8; n++) {
            s[n][0] = ex2f(s[n][0] - nm0);
            s[n][1] = ex2f(s[n][1] - nm0);
            s[n][2] = ex2f(s[n][2] - nm1);
            s[n][3] = ex2f(s[n][3] - nm1);
            sum0 += s[n][0] + s[n][1];
            sum1 += s[n][2] + s[n][3];
        }
        sum0 += __shfl_xor_sync(0xffffffffu, sum0, 1);
        sum0 += __shfl_xor_sync(0xffffffffu, sum0, 2);
        sum1 += __shfl_xor_sync(0xffffffffu, sum1, 1);
        sum1 += __shfl_xor_sync(0xffffffffu, sum1, 2);
        li[0] = li[0] * al0 + sum0;
        li[1] = li[1] * al1 + sum1;

#pragma unroll
        for (int n = 0; n < 8; n++) {
            oacc[n][0] *= al0; oacc[n][1] *= al0;
            oacc[n][2] *= al1; oacc[n][3] *= al1;
        }

        // ---- P fragments (hi/lo) + O += P V ----
#pragma unroll
        for (int kk = 0; kk < 4; kk++) {
            float* pA = s[2 * kk];
            float* pB = s[2 * kk + 1];
            uint32_t ph[4], pl[4];
            ph[0] = packbf(pA[0], pA[1]);
            ph[1] = packbf(pA[2], pA[3]);
            ph[2] = packbf(pB[0], pB[1]);
            ph[3] = packbf(pB[2], pB[3]);
            {
                __nv_bfloat162 h0 = *(__nv_bfloat162*)&ph[0];
                __nv_bfloat162 h1 = *(__nv_bfloat162*)&ph[1];
                __nv_bfloat162 h2 = *(__nv_bfloat162*)&ph[2];
                __nv_bfloat162 h3 = *(__nv_bfloat162*)&ph[3];
                pl[0] = packbf(pA[0] - __bfloat162float(h0.x), pA[1] - __bfloat162float(h0.y));
                pl[1] = packbf(pA[2] - __bfloat162float(h1.x), pA[3] - __bfloat162float(h1.y));
                pl[2] = packbf(pB[0] - __bfloat162float(h2.x), pB[1] - __bfloat162float(h2.y));
                pl[3] = packbf(pB[2] - __bfloat162float(h3.x), pB[3] - __bfloat162float(h3.y));
            }
#pragma unroll
            for (int np = 0; np < 4; np++) {
                uint32_t vh0, vh1, vh2, vh3, vl0, vl1, vl2, vl3;
                const int row = kk * 16 + (sub & 1) * 8 + r8;
                const int ch = np * 2 + (sub >> 1);
                const uint32_t off = row * 128 + ((ch ^ (row & 7)) << 4);
                ldm_x4t(vh0, vh1, vh2, vh3, Vb + off);
                ldm_x4t(vl0, vl1, vl2, vl3, Vb + FKV_TILE + off);
                uint32_t bh0[2] = {vh0, vh1}, bh1[2] = {vh2, vh3};
                uint32_t bl0[2] = {vl0, vl1}, bl1[2] = {vl2, vl3};
                mma_bf16(oacc[np * 2], ph, bh0);
                mma_bf16(oacc[np * 2], ph, bl0);
                mma_bf16(oacc[np * 2], pl, bh0);
                mma_bf16(oacc[np * 2 + 1], ph, bh1);
                mma_bf16(oacc[np * 2 + 1], ph, bl1);
                mma_bf16(oacc[np * 2 + 1], pl, bh1);
            }
        }
    }

    // ---- epilogue: O / li -> bf16 hi/lo ----
    const float inv0 = 1.0f / li[0], inv1 = 1.0f / li[1];
#pragma unroll
    for (int n = 0; n < 8; n++) {
        const int col = h * DK + n * 8 + (lane & 3) * 2;
#pragma unroll
        for (int half = 0; half < 2; half++) {
            const float inv = half ? inv1 : inv0;
            const int row = b * SS + q0 + warp * 16 + (lane >> 2) + half * 8;
            const float a0 = oacc[n][half * 2 + 0] * inv;
            const float a1 = oacc[n][half * 2 + 1] * inv;
            __nv_bfloat162 hv = __floats2bfloat162_rn(a0, a1);
            __nv_bfloat162 lv = __floats2bfloat162_rn(
                a0 - __bfloat162float(hv.x), a1 - __bfloat162float(hv.y));
            *(__nv_bfloat162*)(oh + (size_t)row * DD + col) = hv;
            *(__nv_bfloat162*)(ol + (size_t)row * DD + col) = lv;
        }
    }
}

// ---------------------------------------------------------------------------
extern "C" void kernel_launch(void* const* d_in, const int* in_sizes, int n_in,
                              void* d_out, int out_size)
{
    const float* x  = (const float*)d_in[0];
    const float* rc = (const float*)d_in[1];
    const float* rs = (const float*)d_in[2];
    // d_in[3] = mask (causal; handled analytically)
    const float* w_in[4] = {(const float*)d_in[4], (const float*)d_in[5],
                            (const float*)d_in[6], (const float*)d_in[7]};
    float* out = (float*)d_out;

    __nv_bfloat16 *xh, *xl, *qh, *ql, *kh, *kl, *vh, *vl, *oh, *ol, *wh, *wl;
    cudaGetSymbolAddress((void**)&xh, g_xh);
    cudaGetSymbolAddress((void**)&xl, g_xl);
    cudaGetSymbolAddress((void**)&qh, g_qh);
    cudaGetSymbolAddress((void**)&ql, g_ql);
    cudaGetSymbolAddress((void**)&kh, g_kh);
    cudaGetSymbolAddress((void**)&kl, g_kl);
    cudaGetSymbolAddress((void**)&vh, g_vh);
    cudaGetSymbolAddress((void**)&vl, g_vl);
    cudaGetSymbolAddress((void**)&oh, g_oh);
    cudaGetSymbolAddress((void**)&ol, g_ol);
    cudaGetSymbolAddress((void**)&wh, g_wh);
    cudaGetSymbolAddress((void**)&wl, g_wl);

    cudaFuncSetAttribute(gemm_mma_kernel,
                         cudaFuncAttributeMaxDynamicSharedMemorySize, GEMM_SMEM);
    cudaFuncSetAttribute(flash_tc_kernel,
                         cudaFuncAttributeMaxDynamicSharedMemorySize, FLASH_SMEM);

    // 1) splits: x and the four weight matrices
    split_kernel<<<(MM * DD / 4 + 255) / 256, 256>>>((const float4*)x, xh, xl, MM * DD / 4);
    for (int i = 0; i < 4; i++) {
        split_kernel<<<(DD * DD / 4 + 255) / 256, 256>>>(
            (const float4*)w_in[i], wh + (size_t)i * DD * DD,
            wl + (size_t)i * DD * DD, DD * DD / 4);
    }

    // 2) fused QKV projections (+RoPE on Q,K), bf16 hi/lo outputs
    GemmArgs aq{};
    aq.Ah = xh; aq.Al = xl;
    aq.Wh[0] = wh;                   aq.Wl[0] = wl;
    aq.Wh[1] = wh + (size_t)DD*DD;   aq.Wl[1] = wl + (size_t)DD*DD;
    aq.Wh[2] = wh + (size_t)2*DD*DD; aq.Wl[2] = wl + (size_t)2*DD*DD;
    aq.Ch[0] = qh; aq.Cl[0] = ql;
    aq.Ch[1] = kh; aq.Cl[1] = kl;
    aq.Ch[2] = vh; aq.Cl[2] = vl;
    aq.Cf = nullptr;
    aq.rc = rc; aq.rs = rs; aq.nz_rope = 2; aq.out_bf16 = 1;
    gemm_mma_kernel<<<dim3(DD / 128, MM / 128, 3), 256, GEMM_SMEM>>>(aq);

    // 3) tensor-core flash attention
    flash_tc_kernel<<<dim3(SS / 128, BB * HH), 256, FLASH_SMEM>>>(
        qh, ql, kh, kl, vh, vl, oh, ol);

    // 4) output projection (fp32 out)
    GemmArgs ao{};
    ao.Ah = oh; ao.Al = ol;
    ao.Wh[0] = wh + (size_t)3*DD*DD; ao.Wl[0] = wl + (size_t)3*DD*DD;
    ao.Wh[1] = ao.Wh[0]; ao.Wh[2] = ao.Wh[0];
    ao.Wl[1] = ao.Wl[0]; ao.Wl[2] = ao.Wl[0];
    ao.Cf = out;
    ao.rc = rc; ao.rs = rs; ao.nz_rope = 0; ao.out_bf16 = 0;
    gemm_mma_kernel<<<dim3(DD / 128, MM / 128, 1), 256, GEMM_SMEM>>>(ao);
}

// round 6
// speedup vs baseline: 3.8402x; 1.3157x over previous
#include <cuda_runtime.h>
#include <cuda_fp16.h>
#include <math.h>
#include <cstdint>

// Problem constants
#define BB 2
#define SS 2048
#define DD 1024
#define HH 16
#define DK 64
#define MM (BB * SS)   // 4096

// Scratch (device globals: allocation rules forbid cudaMalloc)
__device__ __half g_xh[MM * DD];
__device__ __half g_xl[MM * DD];
__device__ __half g_qh[MM * DD];
__device__ __half g_kh[MM * DD];
__device__ __half g_vh[MM * DD];
__device__ __half g_vl[MM * DD];
__device__ __half g_oh[MM * DD];
__device__ __half g_ol[MM * DD];
__device__ __half g_wh[4][DD * DD];
__device__ __half g_wl[4][DD * DD];

// ---------------------------------------------------------------------------
// Helpers (sm_80-baseline PTX: ldmatrix / mma.sync / cp.async)
// ---------------------------------------------------------------------------
__device__ __forceinline__ uint32_t smem_u32(const void* p) {
    uint32_t a;
    asm("{ .reg .u64 t; cvta.to.shared.u64 t, %1; cvt.u32.u64 %0, t; }" : "=r"(a) : "l"(p));
    return a;
}
__device__ __forceinline__ void cpa16(uint32_t s, const void* g) {
    asm volatile("cp.async.cg.shared.global [%0], [%1], 16;" :: "r"(s), "l"(g));
}
#define CP_COMMIT() asm volatile("cp.async.commit_group;")
#define CP_WAIT(n)  asm volatile("cp.async.wait_group %0;" :: "n"(n))

__device__ __forceinline__ void ldm_x4(uint32_t& r0, uint32_t& r1, uint32_t& r2,
                                       uint32_t& r3, uint32_t addr) {
    asm volatile("ldmatrix.sync.aligned.m8n8.x4.shared.b16 {%0,%1,%2,%3}, [%4];"
                 : "=r"(r0), "=r"(r1), "=r"(r2), "=r"(r3) : "r"(addr));
}
__device__ __forceinline__ void ldm_x4t(uint32_t& r0, uint32_t& r1, uint32_t& r2,
                                        uint32_t& r3, uint32_t addr) {
    asm volatile("ldmatrix.sync.aligned.m8n8.x4.trans.shared.b16 {%0,%1,%2,%3}, [%4];"
                 : "=r"(r0), "=r"(r1), "=r"(r2), "=r"(r3) : "r"(addr));
}
__device__ __forceinline__ void mma_f16(float* d, const uint32_t* a, const uint32_t* b) {
    asm volatile(
        "mma.sync.aligned.m16n8k16.row.col.f32.f16.f16.f32 "
        "{%0,%1,%2,%3}, {%4,%5,%6,%7}, {%8,%9}, {%0,%1,%2,%3};"
        : "+f"(d[0]), "+f"(d[1]), "+f"(d[2]), "+f"(d[3])
        : "r"(a[0]), "r"(a[1]), "r"(a[2]), "r"(a[3]), "r"(b[0]), "r"(b[1]));
}
__device__ __forceinline__ float ex2f(float x) {
    float r;
    asm("ex2.approx.f32 %0, %1;" : "=f"(r) : "f"(x));
    return r;
}
__device__ __forceinline__ uint32_t packh(float a, float b) {
    __half2 t = __floats2half2_rn(a, b);
    return *(uint32_t*)&t;
}

// ---------------------------------------------------------------------------
// Split fp32 -> (fp16 hi, fp16 residual lo)
// ---------------------------------------------------------------------------
__global__ __launch_bounds__(256)
void split_kernel(const float4* __restrict__ src,
                  __half* __restrict__ hi,
                  __half* __restrict__ lo, int n4)
{
    int i = blockIdx.x * 256 + threadIdx.x;
    if (i < n4) {
        float4 s = src[i];
        __half2 h01 = __floats2half2_rn(s.x, s.y);
        __half2 h23 = __floats2half2_rn(s.z, s.w);
        *(__half2*)(hi + 4 * (size_t)i)     = h01;
        *(__half2*)(hi + 4 * (size_t)i + 2) = h23;
        *(__half2*)(lo + 4 * (size_t)i) = __floats2half2_rn(
            s.x - __half2float(h01.x), s.y - __half2float(h01.y));
        *(__half2*)(lo + 4 * (size_t)i + 2) = __floats2half2_rn(
            s.z - __half2float(h23.x), s.w - __half2float(h23.y));
    }
}

// ---------------------------------------------------------------------------
// mma.sync fp16 GEMM with variable term count: C[m,n] = sum_k A[m,k]*W[n,k].
// nt=1: Ah*Wh.  nt=3: + Ah*Wl + Al*Wh (fp16x3 compensation).
// 128x128 tile, BK=32, 8 warps (4 m x 2 n), 3-stage cp.async pipeline.
// Epilogue: optional RoPE; output fp32 (Cf) or fp16 hi(/lo if nt==3).
// ---------------------------------------------------------------------------
struct GemmArgs {
    const __half* Ah; const __half* Al;
    const __half* Wh[3]; const __half* Wl[3];
    __half* Ch[3]; __half* Cl[3];
    float* Cf;
    const float* rc; const float* rs;
    int nz_rope; int out_half;
    int nt[3];
};

#define TILE_BYTES 16384            // 128 rows x 128B (hi 64B | lo 64B)
#define STAGE_BYTES (2 * TILE_BYTES)
#define GEMM_SMEM (3 * STAGE_BYTES) // 98304

__global__ __launch_bounds__(256)
void gemm_mma_kernel(GemmArgs p)
{
    extern __shared__ char smem[];
    const uint32_t sb = smem_u32(smem);
    const int tid = threadIdx.x;
    const int lane = tid & 31, wid = tid >> 5;
    const int warp_m = wid & 3, warp_n = wid >> 2;
    const int z = blockIdx.z;
    const int n0 = blockIdx.x * 128, m0 = blockIdx.y * 128;
    const int nt = p.nt[z];
    const bool needAl = (nt >= 3), needWl = (nt >= 2);

    const __half* srcs[4] = {
        p.Ah + (size_t)m0 * DD, p.Al + (size_t)m0 * DD,
        p.Wh[z] + (size_t)n0 * DD, p.Wl[z] + (size_t)n0 * DD };

    // loader: tl 0=Ah,1=Al,2=Wh,3=Wl; 512 cpa16 per sub-tile.
    auto load_chunk = [&](int c, int st) {
        const uint32_t sbase = sb + st * STAGE_BYTES;
#pragma unroll
        for (int tl = 0; tl < 4; tl++) {
            if (tl == 1 && !needAl) continue;
            if (tl == 3 && !needWl) continue;
#pragma unroll
            for (int i = 0; i < 2; i++) {
                const int t = tid + i * 256;       // 0..511
                const int row = t >> 2, c4 = t & 3;
                const int ch = (tl & 1) ? c4 + 4 : c4;
                cpa16(sbase + (tl >> 1) * TILE_BYTES + row * 128 + ((ch ^ (row & 7)) << 4),
                      srcs[tl] + (size_t)row * DD + c * 32 + c4 * 8);
            }
        }
    };

    float acc[2][8][4];
#pragma unroll
    for (int m = 0; m < 2; m++)
#pragma unroll
        for (int n = 0; n < 8; n++)
#pragma unroll
            for (int j = 0; j < 4; j++) acc[m][n][j] = 0.f;

    load_chunk(0, 0); CP_COMMIT();
    load_chunk(1, 1); CP_COMMIT();

    const int sub = lane >> 3, r8 = lane & 7;

    for (int c = 0; c < 32; c++) {
        __syncthreads();
        if (c + 2 < 32) load_chunk(c + 2, (c + 2) % 3);
        CP_COMMIT();
        CP_WAIT(2);
        __syncthreads();

        const uint32_t Ab = sb + (c % 3) * STAGE_BYTES;
        const uint32_t Wb = Ab + TILE_BYTES;

#pragma unroll
        for (int ka = 0; ka < 2; ka++) {
            uint32_t afh[2][4], afl[2][4];
#pragma unroll
            for (int m = 0; m < 2; m++) {
                const int row = warp_m * 32 + m * 16 + (sub & 1) * 8 + r8;
                const int chh = ka * 2 + (sub >> 1);
                ldm_x4(afh[m][0], afh[m][1], afh[m][2], afh[m][3],
                       Ab + row * 128 + ((chh ^ (row & 7)) << 4));
                if (needAl) {
                    const int chl = 4 + ka * 2 + (sub >> 1);
                    ldm_x4(afl[m][0], afl[m][1], afl[m][2], afl[m][3],
                           Ab + row * 128 + ((chl ^ (row & 7)) << 4));
                }
            }
            uint32_t bfh[8][2], bfl[8][2];
#pragma unroll
            for (int np = 0; np < 4; np++) {
                const int row = warp_n * 64 + np * 16 + (sub >> 1) * 8 + r8;
                const int chh = ka * 2 + (sub & 1);
                uint32_t r0, r1, r2, r3;
                ldm_x4(r0, r1, r2, r3, Wb + row * 128 + ((chh ^ (row & 7)) << 4));
                bfh[np * 2][0] = r0;     bfh[np * 2][1] = r1;
                bfh[np * 2 + 1][0] = r2; bfh[np * 2 + 1][1] = r3;
                if (needWl) {
                    const int chl = 4 + ka * 2 + (sub & 1);
                    ldm_x4(r0, r1, r2, r3, Wb + row * 128 + ((chl ^ (row & 7)) << 4));
                    bfl[np * 2][0] = r0;     bfl[np * 2][1] = r1;
                    bfl[np * 2 + 1][0] = r2; bfl[np * 2 + 1][1] = r3;
                }
            }
#pragma unroll
            for (int m = 0; m < 2; m++)
#pragma unroll
                for (int n = 0; n < 8; n++) {
                    mma_f16(acc[m][n], afh[m], bfh[n]);
                    if (needWl) mma_f16(acc[m][n], afh[m], bfl[n]);
                    if (needAl) mma_f16(acc[m][n], afl[m], bfh[n]);
                }
        }
    }

    const bool rope = (z < p.nz_rope);
    const int lane4 = lane >> 2, lanem = lane & 3;
#pragma unroll
    for (int m = 0; m < 2; m++)
#pragma unroll
        for (int n = 0; n < 8; n++) {
            const int col = n0 + warp_n * 64 + n * 8 + lanem * 2;
#pragma unroll
            for (int half = 0; half < 2; half++) {
                const int row = m0 + warp_m * 32 + m * 16 + lane4 + half * 8;
                float a0 = acc[m][n][half * 2 + 0];
                float a1 = acc[m][n][half * 2 + 1];
                if (rope) {
                    const int s = row & (SS - 1);
                    const int pi = (col & (DK - 1)) >> 1;
                    const float cc = p.rc[s * (DK / 2) + pi];
                    const float sn = p.rs[s * (DK / 2) + pi];
                    const float t0 = a0 * cc - a1 * sn;
                    const float t1 = a0 * sn + a1 * cc;
                    a0 = t0; a1 = t1;
                }
                if (p.out_half) {
                    __half2 h = __floats2half2_rn(a0, a1);
                    *(__half2*)(p.Ch[z] + (size_t)row * DD + col) = h;
                    if (nt >= 3) {
                        *(__half2*)(p.Cl[z] + (size_t)row * DD + col) =
                            __floats2half2_rn(a0 - __half2float(h.x),
                                              a1 - __half2float(h.y));
                    }
                } else {
                    *(float2*)(p.Cf + (size_t)row * DD + col) = make_float2(a0, a1);
                }
            }
        }
}

// ---------------------------------------------------------------------------
// Tensor-core flash attention (causal), fp16.
// QK^T: 1 term (q,k fp16; logit attenuation makes this safe).
// PV: 3 terms (P hi/lo x V hi + P hi x V lo).
// Q tile 128 rows, KV steps 64, 8 warps, 256 threads.
// Smem: Qh[128][64] + 2 stages of {Kh,Vh,Vl}[64][64], 128B swizzled rows.
// ---------------------------------------------------------------------------
#define FQ_BYTES 16384              // 128 rows * 128B
#define FKV_TILE 8192               // 64 rows * 128B
#define FSTAGE (3 * FKV_TILE)       // 24576
#define FLASH_SMEM (FQ_BYTES + 2 * FSTAGE)   // 65536

__global__ __launch_bounds__(256)
void flash_tc_kernel(const __half* __restrict__ qh,
                     const __half* __restrict__ kh,
                     const __half* __restrict__ vh,
                     const __half* __restrict__ vl,
                     __half* __restrict__ oh,
                     __half* __restrict__ ol)
{
    extern __shared__ char smem[];
    const uint32_t sb = smem_u32(smem);
    const int tid = threadIdx.x;
    const int lane = tid & 31, warp = tid >> 5;
    const int sub = lane >> 3, r8 = lane & 7;
    const int qtile = (int)gridDim.x - 1 - (int)blockIdx.x;   // heavy tiles first
    const int bh = blockIdx.y;
    const int b = bh / HH, h = bh % HH;
    const int q0 = qtile * 128;
    const int njt = 2 * qtile + 2;
    const size_t gbase = (size_t)b * SS * DD + h * DK;

    const __half* kvsrc[3] = {kh + gbase, vh + gbase, vl + gbase};

    // ---- load Q tile (hi only) ----
#pragma unroll
    for (int i = 0; i < 4; i++) {
        const int s = tid + i * 256;         // 0..1023
        const int row = s >> 3, ch = s & 7;
        cpa16(sb + row * 128 + ((ch ^ (row & 7)) << 4),
              qh + gbase + (size_t)(q0 + row) * DD + ch * 8);
    }
    auto load_kv = [&](int jt, int st) {
        const int k0 = jt * 64;
#pragma unroll
        for (int i = 0; i < 6; i++) {
            const int s = tid + i * 256;     // 0..1535
            const int tile = s >> 9;         // Kh, Vh, Vl
            const int t = s & 511;
            const int row = t >> 3, ch = t & 7;
            cpa16(sb + FQ_BYTES + st * FSTAGE + tile * FKV_TILE +
                      row * 128 + ((ch ^ (row & 7)) << 4),
                  kvsrc[tile] + (size_t)(k0 + row) * DD + ch * 8);
        }
    };
    load_kv(0, 0);
    CP_COMMIT();
    CP_WAIT(0);
    __syncthreads();

    // ---- Q fragments register-resident: [katom][4] ----
    uint32_t qfr[4][4];
#pragma unroll
    for (int ka = 0; ka < 4; ka++) {
        const int row = warp * 16 + (sub & 1) * 8 + r8;
        const int ch = ka * 2 + (sub >> 1);
        ldm_x4(qfr[ka][0], qfr[ka][1], qfr[ka][2], qfr[ka][3],
               sb + row * 128 + ((ch ^ (row & 7)) << 4));
    }

    float oacc[8][4];
#pragma unroll
    for (int n = 0; n < 8; n++)
#pragma unroll
        for (int j = 0; j < 4; j++) oacc[n][j] = 0.f;
    float mi[2] = {-INFINITY, -INFINITY};
    float li[2] = {0.f, 0.f};

    const float C2 = 1.4426950408889634f / 64.0f;   // log2(e)/64
    const int qrow0 = q0 + warp * 16 + (lane >> 2);

    for (int jt = 0; jt < njt; jt++) {
        const int buf = jt & 1;
        const int k0 = jt * 64;
        __syncthreads();
        if (jt + 1 < njt) { load_kv(jt + 1, 1 - buf); CP_COMMIT(); CP_WAIT(1); }
        else             { CP_WAIT(0); }
        __syncthreads();

        const uint32_t Kb  = sb + FQ_BYTES + buf * FSTAGE;
        const uint32_t Vb  = Kb + FKV_TILE;
        const uint32_t Vlb = Kb + 2 * FKV_TILE;

        // ---- S = Q K^T (1 term) ----
        float s[8][4];
#pragma unroll
        for (int n = 0; n < 8; n++)
#pragma unroll
            for (int j = 0; j < 4; j++) s[n][j] = 0.f;

#pragma unroll
        for (int ka = 0; ka < 4; ka++) {
            uint32_t bfr[8][2];
#pragma unroll
            for (int np = 0; np < 4; np++) {
                const int row = np * 16 + (sub >> 1) * 8 + r8;
                const int ch = ka * 2 + (sub & 1);
                uint32_t r0, r1, r2, r3;
                ldm_x4(r0, r1, r2, r3, Kb + row * 128 + ((ch ^ (row & 7)) << 4));
                bfr[np * 2][0] = r0;     bfr[np * 2][1] = r1;
                bfr[np * 2 + 1][0] = r2; bfr[np * 2 + 1][1] = r3;
            }
#pragma unroll
            for (int n = 0; n < 8; n++)
                mma_f16(s[n], qfr[ka], bfr[n]);
        }

        // ---- scale + mask ----
        const bool need_mask = (k0 + 64 > qrow0);
#pragma unroll
        for (int n = 0; n < 8; n++) {
            const int col = k0 + n * 8 + (lane & 3) * 2;
#pragma unroll
            for (int j = 0; j < 4; j++) {
                float v = s[n][j] * C2;
                if (need_mask) {
                    const int kv = col + (j & 1);
                    const int qr = qrow0 + (j >> 1) * 8;
                    if (kv > qr) v = -1e30f;
                }
                s[n][j] = v;
            }
        }

        // ---- online softmax ----
        float mx0 = s[0][0], mx1 = s[0][2];
#pragma unroll
        for (int n = 0; n < 8; n++) {
            mx0 = fmaxf(mx0, fmaxf(s[n][0], s[n][1]));
            mx1 = fmaxf(mx1, fmaxf(s[n][2], s[n][3]));
        }
        mx0 = fmaxf(mx0, __shfl_xor_sync(0xffffffffu, mx0, 1));
        mx0 = fmaxf(mx0, __shfl_xor_sync(0xffffffffu, mx0, 2));
        mx1 = fmaxf(mx1, __shfl_xor_sync(0xffffffffu, mx1, 1));
        mx1 = fmaxf(mx1, __shfl_xor_sync(0xffffffffu, mx1, 2));
        const float nm0 = fmaxf(mi[0], mx0), nm1 = fmaxf(mi[1], mx1);
        const float al0 = ex2f(mi[0] - nm0), al1 = ex2f(mi[1] - nm1);
        mi[0] = nm0; mi[1] = nm1;

        float sum0 = 0.f, sum1 = 0.f;
#pragma unroll
        for (int n = 0; n < 8; n++) {
            s[n][0] = ex2f(s[n][0] - nm0);
            s[n][1] = ex2f(s[n][1] - nm0);
            s[n][2] = ex2f(s[n][2] - nm1);
            s[n][3] = ex2f(s[n][3] - nm1);
            sum0 += s[n][0] + s[n][1];
            sum1 += s[n][2] + s[n][3];
        }
        sum0 += __shfl_xor_sync(0xffffffffu, sum0, 1);
        sum0 += __shfl_xor_sync(0xffffffffu, sum0, 2);
        sum1 += __shfl_xor_sync(0xffffffffu, sum1, 1);
        sum1 += __shfl_xor_sync(0xffffffffu, sum1, 2);
        li[0] = li[0] * al0 + sum0;
        li[1] = li[1] * al1 + sum1;

#pragma unroll
        for (int n = 0; n < 8; n++) {
            oacc[n][0] *= al0; oacc[n][1] *= al0;
            oacc[n][2] *= al1; oacc[n][3] *= al1;
        }

        // ---- P fragments (hi/lo) + O += P V (3-term) ----
#pragma unroll
        for (int kk = 0; kk < 4; kk++) {
            float* pA = s[2 * kk];
            float* pB = s[2 * kk + 1];
            uint32_t ph[4], pl[4];
            ph[0] = packh(pA[0], pA[1]);
            ph[1] = packh(pA[2], pA[3]);
            ph[2] = packh(pB[0], pB[1]);
            ph[3] = packh(pB[2], pB[3]);
            {
                __half2 h0 = *(__half2*)&ph[0];
                __half2 h1 = *(__half2*)&ph[1];
                __half2 h2 = *(__half2*)&ph[2];
                __half2 h3 = *(__half2*)&ph[3];
                pl[0] = packh(pA[0] - __half2float(h0.x), pA[1] - __half2float(h0.y));
                pl[1] = packh(pA[2] - __half2float(h1.x), pA[3] - __half2float(h1.y));
                pl[2] = packh(pB[0] - __half2float(h2.x), pB[1] - __half2float(h2.y));
                pl[3] = packh(pB[2] - __half2float(h3.x), pB[3] - __half2float(h3.y));
            }
#pragma unroll
            for (int np = 0; np < 4; np++) {
                uint32_t vh0, vh1, vh2, vh3, vl0, vl1, vl2, vl3;
                const int row = kk * 16 + (sub & 1) * 8 + r8;
                const int ch = np * 2 + (sub >> 1);
                const uint32_t off = row * 128 + ((ch ^ (row & 7)) << 4);
                ldm_x4t(vh0, vh1, vh2, vh3, Vb + off);
                ldm_x4t(vl0, vl1, vl2, vl3, Vlb + off);
                uint32_t bh0[2] = {vh0, vh1}, bh1[2] = {vh2, vh3};
                uint32_t bl0[2] = {vl0, vl1}, bl1[2] = {vl2, vl3};
                mma_f16(oacc[np * 2], ph, bh0);
                mma_f16(oacc[np * 2], pl, bh0);
                mma_f16(oacc[np * 2], ph, bl0);
                mma_f16(oacc[np * 2 + 1], ph, bh1);
                mma_f16(oacc[np * 2 + 1], pl, bh1);
                mma_f16(oacc[np * 2 + 1], ph, bl1);
            }
        }
    }

    // ---- epilogue: O / li -> fp16 hi/lo ----
    const float inv0 = 1.0f / li[0], inv1 = 1.0f / li[1];
#pragma unroll
    for (int n = 0; n < 8; n++) {
        const int col = h * DK + n * 8 + (lane & 3) * 2;
#pragma unroll
        for (int half = 0; half < 2; half++) {
            const float inv = half ? inv1 : inv0;
            const int row = b * SS + q0 + warp * 16 + (lane >> 2) + half * 8;
            const float a0 = oacc[n][half * 2 + 0] * inv;
            const float a1 = oacc[n][half * 2 + 1] * inv;
            __half2 hv = __floats2half2_rn(a0, a1);
            *(__half2*)(oh + (size_t)row * DD + col) = hv;
            *(__half2*)(ol + (size_t)row * DD + col) = __floats2half2_rn(
                a0 - __half2float(hv.x), a1 - __half2float(hv.y));
        }
    }
}

// ---------------------------------------------------------------------------
extern "C" void kernel_launch(void* const* d_in, const int* in_sizes, int n_in,
                              void* d_out, int out_size)
{
    const float* x  = (const float*)d_in[0];
    const float* rc = (const float*)d_in[1];
    const float* rs = (const float*)d_in[2];
    // d_in[3] = mask (causal; handled analytically)
    const float* w_in[4] = {(const float*)d_in[4], (const float*)d_in[5],
                            (const float*)d_in[6], (const float*)d_in[7]};
    float* out = (float*)d_out;

    __half *xh, *xl, *qh, *kh, *vh, *vl, *oh, *ol, *wh, *wl;
    cudaGetSymbolAddress((void**)&xh, g_xh);
    cudaGetSymbolAddress((void**)&xl, g_xl);
    cudaGetSymbolAddress((void**)&qh, g_qh);
    cudaGetSymbolAddress((void**)&kh, g_kh);
    cudaGetSymbolAddress((void**)&vh, g_vh);
    cudaGetSymbolAddress((void**)&vl, g_vl);
    cudaGetSymbolAddress((void**)&oh, g_oh);
    cudaGetSymbolAddress((void**)&ol, g_ol);
    cudaGetSymbolAddress((void**)&wh, g_wh);
    cudaGetSymbolAddress((void**)&wl, g_wl);

    cudaFuncSetAttribute(gemm_mma_kernel,
                         cudaFuncAttributeMaxDynamicSharedMemorySize, GEMM_SMEM);
    cudaFuncSetAttribute(flash_tc_kernel,
                         cudaFuncAttributeMaxDynamicSharedMemorySize, FLASH_SMEM);

    // 1) splits: x and the four weight matrices
    split_kernel<<<(MM * DD / 4 + 255) / 256, 256>>>((const float4*)x, xh, xl, MM * DD / 4);
    for (int i = 0; i < 4; i++) {
        split_kernel<<<(DD * DD / 4 + 255) / 256, 256>>>(
            (const float4*)w_in[i], wh + (size_t)i * DD * DD,
            wl + (size_t)i * DD * DD, DD * DD / 4);
    }

    // 2) fused QKV projections (+RoPE on Q,K); Q,K 1-term, V 3-term
    GemmArgs aq{};
    aq.Ah = xh; aq.Al = xl;
    aq.Wh[0] = wh;                   aq.Wl[0] = wl;
    aq.Wh[1] = wh + (size_t)DD*DD;   aq.Wl[1] = wl + (size_t)DD*DD;
    aq.Wh[2] = wh + (size_t)2*DD*DD; aq.Wl[2] = wl + (size_t)2*DD*DD;
    aq.Ch[0] = qh; aq.Cl[0] = qh;    // Q: no lo written (nt=1)
    aq.Ch[1] = kh; aq.Cl[1] = kh;
    aq.Ch[2] = vh; aq.Cl[2] = vl;
    aq.Cf = nullptr;
    aq.rc = rc; aq.rs = rs; aq.nz_rope = 2; aq.out_half = 1;
    aq.nt[0] = 1; aq.nt[1] = 1; aq.nt[2] = 3;
    gemm_mma_kernel<<<dim3(DD / 128, MM / 128, 3), 256, GEMM_SMEM>>>(aq);

    // 3) tensor-core flash attention
    flash_tc_kernel<<<dim3(SS / 128, BB * HH), 256, FLASH_SMEM>>>(
        qh, kh, vh, vl, oh, ol);

    // 4) output projection (3-term, fp32 out)
    GemmArgs ao{};
    ao.Ah = oh; ao.Al = ol;
    ao.Wh[0] = wh + (size_t)3*DD*DD; ao.Wl[0] = wl + (size_t)3*DD*DD;
    ao.Wh[1] = ao.Wh[0]; ao.Wh[2] = ao.Wh[0];
    ao.Wl[1] = ao.Wl[0]; ao.Wl[2] = ao.Wl[0];
    ao.Cf = out;
    ao.rc = rc; ao.rs = rs; ao.nz_rope = 0; ao.out_half = 0;
    ao.nt[0] = 3; ao.nt[1] = 3; ao.nt[2] = 3;
    gemm_mma_kernel<<<dim3(DD / 128, MM / 128, 1), 256, GEMM_SMEM>>>(ao);
}

// round 7
// speedup vs baseline: 4.5558x; 1.1864x over previous
#include <cuda_runtime.h>
#include <cuda_fp16.h>
#include <math.h>
#include <cstdint>

// Problem constants
#define BB 2
#define SS 2048
#define DD 1024
#define HH 16
#define DK 64
#define MM (BB * SS)   // 4096

// Scratch (device globals: allocation rules forbid cudaMalloc)
__device__ __half g_xh[MM * DD];
__device__ __half g_qh[MM * DD];
__device__ __half g_kh[MM * DD];
__device__ __half g_vh[MM * DD];
__device__ __half g_vl[MM * DD];
__device__ __half g_oh[MM * DD];
__device__ __half g_wh[4][DD * DD];
__device__ __half g_wl[4][DD * DD];

// ---------------------------------------------------------------------------
// Helpers (sm_80-baseline PTX: ldmatrix / mma.sync / cp.async)
// ---------------------------------------------------------------------------
__device__ __forceinline__ uint32_t smem_u32(const void* p) {
    uint32_t a;
    asm("{ .reg .u64 t; cvta.to.shared.u64 t, %1; cvt.u32.u64 %0, t; }" : "=r"(a) : "l"(p));
    return a;
}
__device__ __forceinline__ void cpa16(uint32_t s, const void* g) {
    asm volatile("cp.async.cg.shared.global [%0], [%1], 16;" :: "r"(s), "l"(g));
}
#define CP_COMMIT() asm volatile("cp.async.commit_group;")
#define CP_WAIT(n)  asm volatile("cp.async.wait_group %0;" :: "n"(n))

__device__ __forceinline__ void ldm_x4(uint32_t& r0, uint32_t& r1, uint32_t& r2,
                                       uint32_t& r3, uint32_t addr) {
    asm volatile("ldmatrix.sync.aligned.m8n8.x4.shared.b16 {%0,%1,%2,%3}, [%4];"
                 : "=r"(r0), "=r"(r1), "=r"(r2), "=r"(r3) : "r"(addr));
}
__device__ __forceinline__ void ldm_x4t(uint32_t& r0, uint32_t& r1, uint32_t& r2,
                                        uint32_t& r3, uint32_t addr) {
    asm volatile("ldmatrix.sync.aligned.m8n8.x4.trans.shared.b16 {%0,%1,%2,%3}, [%4];"
                 : "=r"(r0), "=r"(r1), "=r"(r2), "=r"(r3) : "r"(addr));
}
__device__ __forceinline__ void mma_f16(float* d, const uint32_t* a, const uint32_t* b) {
    asm volatile(
        "mma.sync.aligned.m16n8k16.row.col.f32.f16.f16.f32 "
        "{%0,%1,%2,%3}, {%4,%5,%6,%7}, {%8,%9}, {%0,%1,%2,%3};"
        : "+f"(d[0]), "+f"(d[1]), "+f"(d[2]), "+f"(d[3])
        : "r"(a[0]), "r"(a[1]), "r"(a[2]), "r"(a[3]), "r"(b[0]), "r"(b[1]));
}
__device__ __forceinline__ float ex2f(float x) {
    float r;
    asm("ex2.approx.f32 %0, %1;" : "=f"(r) : "f"(x));
    return r;
}
__device__ __forceinline__ uint32_t packh(float a, float b) {
    __half2 t = __floats2half2_rn(a, b);
    return *(uint32_t*)&t;
}

// ---------------------------------------------------------------------------
// Convert fp32 -> fp16 (hi only)
// ---------------------------------------------------------------------------
__global__ __launch_bounds__(256)
void cvt_kernel(const float4* __restrict__ src, __half* __restrict__ hi, int n4)
{
    int i = blockIdx.x * 256 + threadIdx.x;
    if (i < n4) {
        float4 s = src[i];
        *(__half2*)(hi + 4 * (size_t)i)     = __floats2half2_rn(s.x, s.y);
        *(__half2*)(hi + 4 * (size_t)i + 2) = __floats2half2_rn(s.z, s.w);
    }
}

// ---------------------------------------------------------------------------
// Fused weight split: 4 matrices fp32 -> (fp16 hi, fp16 residual lo)
// grid (n4, 4)
// ---------------------------------------------------------------------------
struct WSplitArgs { const float4* src[4]; __half* hi; __half* lo; };

__global__ __launch_bounds__(256)
void wsplit_kernel(WSplitArgs a)
{
    const int w = blockIdx.y;
    const int i = blockIdx.x * 256 + threadIdx.x;     // < DD*DD/4
    float4 s = a.src[w][i];
    __half* hi = a.hi + (size_t)w * DD * DD + 4 * (size_t)i;
    __half* lo = a.lo + (size_t)w * DD * DD + 4 * (size_t)i;
    __half2 h01 = __floats2half2_rn(s.x, s.y);
    __half2 h23 = __floats2half2_rn(s.z, s.w);
    *(__half2*)(hi)     = h01;
    *(__half2*)(hi + 2) = h23;
    *(__half2*)(lo)     = __floats2half2_rn(s.x - __half2float(h01.x),
                                            s.y - __half2float(h01.y));
    *(__half2*)(lo + 2) = __floats2half2_rn(s.z - __half2float(h23.x),
                                            s.w - __half2float(h23.y));
}

// ---------------------------------------------------------------------------
// mma.sync fp16 GEMM: C[m,n] = sum_k A[m,k]*W[n,k], A hi-only.
// nt=1: Ah*Wh.  nt=2: + Ah*Wl (weight compensation).
// 128x128 tile, BK=32, 8 warps (4 m x 2 n), 3-stage cp.async pipeline.
// Epilogue: optional RoPE; out fp32 (Cf) or fp16 hi(+lo if nt>=2).
// ---------------------------------------------------------------------------
struct GemmArgs {
    const __half* Ah;
    const __half* Wh[3]; const __half* Wl[3];
    __half* Ch[3]; __half* Cl[3];
    float* Cf;
    const float* rc; const float* rs;
    int nz_rope; int out_half;
    int nt[3];
};

#define TILE_BYTES 16384            // 128 rows x 128B (A uses ch0-3 only)
#define STAGE_BYTES (2 * TILE_BYTES)
#define GEMM_SMEM (3 * STAGE_BYTES) // 98304

__global__ __launch_bounds__(256)
void gemm_mma_kernel(GemmArgs p)
{
    extern __shared__ char smem[];
    const uint32_t sb = smem_u32(smem);
    const int tid = threadIdx.x;
    const int lane = tid & 31, wid = tid >> 5;
    const int warp_m = wid & 3, warp_n = wid >> 2;
    const int z = blockIdx.z;
    const int n0 = blockIdx.x * 128, m0 = blockIdx.y * 128;
    const int nt = p.nt[z];
    const bool needWl = (nt >= 2);

    const __half* srcA  = p.Ah + (size_t)m0 * DD;
    const __half* srcWh = p.Wh[z] + (size_t)n0 * DD;
    const __half* srcWl = p.Wl[z] + (size_t)n0 * DD;

    auto load_chunk = [&](int c, int st) {
        const uint32_t sbase = sb + st * STAGE_BYTES;
#pragma unroll
        for (int i = 0; i < 2; i++) {
            const int t = tid + i * 256;       // 0..511
            const int row = t >> 2, c4 = t & 3;
            cpa16(sbase + row * 128 + ((c4 ^ (row & 7)) << 4),
                  srcA + (size_t)row * DD + c * 32 + c4 * 8);
        }
#pragma unroll
        for (int i = 0; i < 2; i++) {
            const int t = tid + i * 256;
            const int row = t >> 2, c4 = t & 3;
            cpa16(sbase + TILE_BYTES + row * 128 + ((c4 ^ (row & 7)) << 4),
                  srcWh + (size_t)row * DD + c * 32 + c4 * 8);
        }
        if (needWl) {
#pragma unroll
            for (int i = 0; i < 2; i++) {
                const int t = tid + i * 256;
                const int row = t >> 2, c4 = t & 3;
                const int ch = c4 + 4;
                cpa16(sbase + TILE_BYTES + row * 128 + ((ch ^ (row & 7)) << 4),
                      srcWl + (size_t)row * DD + c * 32 + c4 * 8);
            }
        }
    };

    float acc[2][8][4];
#pragma unroll
    for (int m = 0; m < 2; m++)
#pragma unroll
        for (int n = 0; n < 8; n++)
#pragma unroll
            for (int j = 0; j < 4; j++) acc[m][n][j] = 0.f;

    load_chunk(0, 0); CP_COMMIT();
    load_chunk(1, 1); CP_COMMIT();

    const int sub = lane >> 3, r8 = lane & 7;

    for (int c = 0; c < 32; c++) {
        __syncthreads();
        if (c + 2 < 32) load_chunk(c + 2, (c + 2) % 3);
        CP_COMMIT();
        CP_WAIT(2);
        __syncthreads();

        const uint32_t Ab = sb + (c % 3) * STAGE_BYTES;
        const uint32_t Wb = Ab + TILE_BYTES;

#pragma unroll
        for (int ka = 0; ka < 2; ka++) {
            uint32_t afh[2][4];
#pragma unroll
            for (int m = 0; m < 2; m++) {
                const int row = warp_m * 32 + m * 16 + (sub & 1) * 8 + r8;
                const int chh = ka * 2 + (sub >> 1);
                ldm_x4(afh[m][0], afh[m][1], afh[m][2], afh[m][3],
                       Ab + row * 128 + ((chh ^ (row & 7)) << 4));
            }
            uint32_t bfh[8][2], bfl[8][2];
#pragma unroll
            for (int np = 0; np < 4; np++) {
                const int row = warp_n * 64 + np * 16 + (sub >> 1) * 8 + r8;
                const int chh = ka * 2 + (sub & 1);
                uint32_t r0, r1, r2, r3;
                ldm_x4(r0, r1, r2, r3, Wb + row * 128 + ((chh ^ (row & 7)) << 4));
                bfh[np * 2][0] = r0;     bfh[np * 2][1] = r1;
                bfh[np * 2 + 1][0] = r2; bfh[np * 2 + 1][1] = r3;
                if (needWl) {
                    const int chl = 4 + ka * 2 + (sub & 1);
                    ldm_x4(r0, r1, r2, r3, Wb + row * 128 + ((chl ^ (row & 7)) << 4));
                    bfl[np * 2][0] = r0;     bfl[np * 2][1] = r1;
                    bfl[np * 2 + 1][0] = r2; bfl[np * 2 + 1][1] = r3;
                }
            }
#pragma unroll
            for (int m = 0; m < 2; m++)
#pragma unroll
                for (int n = 0; n < 8; n++) {
                    mma_f16(acc[m][n], afh[m], bfh[n]);
                    if (needWl) mma_f16(acc[m][n], afh[m], bfl[n]);
                }
        }
    }

    const bool rope = (z < p.nz_rope);
    const int lane4 = lane >> 2, lanem = lane & 3;
#pragma unroll
    for (int m = 0; m < 2; m++)
#pragma unroll
        for (int n = 0; n < 8; n++) {
            const int col = n0 + warp_n * 64 + n * 8 + lanem * 2;
#pragma unroll
            for (int half = 0; half < 2; half++) {
                const int row = m0 + warp_m * 32 + m * 16 + lane4 + half * 8;
                float a0 = acc[m][n][half * 2 + 0];
                float a1 = acc[m][n][half * 2 + 1];
                if (rope) {
                    const int s = row & (SS - 1);
                    const int pi = (col & (DK - 1)) >> 1;
                    const float cc = p.rc[s * (DK / 2) + pi];
                    const float sn = p.rs[s * (DK / 2) + pi];
                    const float t0 = a0 * cc - a1 * sn;
                    const float t1 = a0 * sn + a1 * cc;
                    a0 = t0; a1 = t1;
                }
                if (p.out_half) {
                    __half2 h = __floats2half2_rn(a0, a1);
                    *(__half2*)(p.Ch[z] + (size_t)row * DD + col) = h;
                    if (nt >= 2) {
                        *(__half2*)(p.Cl[z] + (size_t)row * DD + col) =
                            __floats2half2_rn(a0 - __half2float(h.x),
                                              a1 - __half2float(h.y));
                    }
                } else {
                    *(float2*)(p.Cf + (size_t)row * DD + col) = make_float2(a0, a1);
                }
            }
        }
}

// ---------------------------------------------------------------------------
// Tensor-core flash attention (causal), fp16.
// QK^T: 1 term.  PV: 2 terms (Ph x Vh + Ph x Vl).
// Q tile 128 rows, KV steps 64, 8 warps, 256 threads.
// ---------------------------------------------------------------------------
#define FQ_BYTES 16384              // 128 rows * 128B
#define FKV_TILE 8192               // 64 rows * 128B
#define FSTAGE (3 * FKV_TILE)       // 24576
#define FLASH_SMEM (FQ_BYTES + 2 * FSTAGE)   // 65536

__global__ __launch_bounds__(256)
void flash_tc_kernel(const __half* __restrict__ qh,
                     const __half* __restrict__ kh,
                     const __half* __restrict__ vh,
                     const __half* __restrict__ vl,
                     __half* __restrict__ oh)
{
    extern __shared__ char smem[];
    const uint32_t sb = smem_u32(smem);
    const int tid = threadIdx.x;
    const int lane = tid & 31, warp = tid >> 5;
    const int sub = lane >> 3, r8 = lane & 7;
    const int qtile = (int)gridDim.x - 1 - (int)blockIdx.x;   // heavy tiles first
    const int bh = blockIdx.y;
    const int b = bh / HH, h = bh % HH;
    const int q0 = qtile * 128;
    const int njt = 2 * qtile + 2;
    const size_t gbase = (size_t)b * SS * DD + h * DK;

    const __half* kvsrc[3] = {kh + gbase, vh + gbase, vl + gbase};

#pragma unroll
    for (int i = 0; i < 4; i++) {
        const int s = tid + i * 256;
        const int row = s >> 3, ch = s & 7;
        cpa16(sb + row * 128 + ((ch ^ (row & 7)) << 4),
              qh + gbase + (size_t)(q0 + row) * DD + ch * 8);
    }
    auto load_kv = [&](int jt, int st) {
        const int k0 = jt * 64;
#pragma unroll
        for (int i = 0; i < 6; i++) {
            const int s = tid + i * 256;
            const int tile = s >> 9;         // Kh, Vh, Vl
            const int t = s & 511;
            const int row = t >> 3, ch = t & 7;
            cpa16(sb + FQ_BYTES + st * FSTAGE + tile * FKV_TILE +
                      row * 128 + ((ch ^ (row & 7)) << 4),
                  kvsrc[tile] + (size_t)(k0 + row) * DD + ch * 8);
        }
    };
    load_kv(0, 0);
    CP_COMMIT();
    CP_WAIT(0);
    __syncthreads();

    uint32_t qfr[4][4];
#pragma unroll
    for (int ka = 0; ka < 4; ka++) {
        const int row = warp * 16 + (sub & 1) * 8 + r8;
        const int ch = ka * 2 + (sub >> 1);
        ldm_x4(qfr[ka][0], qfr[ka][1], qfr[ka][2], qfr[ka][3],
               sb + row * 128 + ((ch ^ (row & 7)) << 4));
    }

    float oacc[8][4];
#pragma unroll
    for (int n = 0; n < 8; n++)
#pragma unroll
        for (int j = 0; j < 4; j++) oacc[n][j] = 0.f;
    float mi[2] = {-INFINITY, -INFINITY};
    float li[2] = {0.f, 0.f};

    const float C2 = 1.4426950408889634f / 64.0f;   // log2(e)/64
    const int qrow0 = q0 + warp * 16 + (lane >> 2);

    for (int jt = 0; jt < njt; jt++) {
        const int buf = jt & 1;
        const int k0 = jt * 64;
        __syncthreads();
        if (jt + 1 < njt) { load_kv(jt + 1, 1 - buf); CP_COMMIT(); CP_WAIT(1); }
        else             { CP_WAIT(0); }
        __syncthreads();

        const uint32_t Kb  = sb + FQ_BYTES + buf * FSTAGE;
        const uint32_t Vb  = Kb + FKV_TILE;
        const uint32_t Vlb = Kb + 2 * FKV_TILE;

        // ---- S = Q K^T (1 term) ----
        float s[8][4];
#pragma unroll
        for (int n = 0; n < 8; n++)
#pragma unroll
            for (int j = 0; j < 4; j++) s[n][j] = 0.f;

#pragma unroll
        for (int ka = 0; ka < 4; ka++) {
            uint32_t bfr[8][2];
#pragma unroll
            for (int np = 0; np < 4; np++) {
                const int row = np * 16 + (sub >> 1) * 8 + r8;
                const int ch = ka * 2 + (sub & 1);
                uint32_t r0, r1, r2, r3;
                ldm_x4(r0, r1, r2, r3, Kb + row * 128 + ((ch ^ (row & 7)) << 4));
                bfr[np * 2][0] = r0;     bfr[np * 2][1] = r1;
                bfr[np * 2 + 1][0] = r2; bfr[np * 2 + 1][1] = r3;
            }
#pragma unroll
            for (int n = 0; n < 8; n++)
                mma_f16(s[n], qfr[ka], bfr[n]);
        }

        // ---- scale + mask ----
        const bool need_mask = (k0 + 64 > qrow0);
#pragma unroll
        for (int n = 0; n < 8; n++) {
            const int col = k0 + n * 8 + (lane & 3) * 2;
#pragma unroll
            for (int j = 0; j < 4; j++) {
                float v = s[n][j] * C2;
                if (need_mask) {
                    const int kv = col + (j & 1);
                    const int qr = qrow0 + (j >> 1) * 8;
                    if (kv > qr) v = -1e30f;
                }
                s[n][j] = v;
            }
        }

        // ---- online softmax ----
        float mx0 = s[0][0], mx1 = s[0][2];
#pragma unroll
        for (int n = 0; n < 8; n++) {
            mx0 = fmaxf(mx0, fmaxf(s[n][0], s[n][1]));
            mx1 = fmaxf(mx1, fmaxf(s[n][2], s[n][3]));
        }
        mx0 = fmaxf(mx0, __shfl_xor_sync(0xffffffffu, mx0, 1));
        mx0 = fmaxf(mx0, __shfl_xor_sync(0xffffffffu, mx0, 2));
        mx1 = fmaxf(mx1, __shfl_xor_sync(0xffffffffu, mx1, 1));
        mx1 = fmaxf(mx1, __shfl_xor_sync(0xffffffffu, mx1, 2));
        const float nm0 = fmaxf(mi[0], mx0), nm1 = fmaxf(mi[1], mx1);
        const float al0 = ex2f(mi[0] - nm0), al1 = ex2f(mi[1] - nm1);
        mi[0] = nm0; mi[1] = nm1;

        float sum0 = 0.f, sum1 = 0.f;
#pragma unroll
        for (int n = 0; n < 8; n++) {
            s[n][0] = ex2f(s[n][0] - nm0);
            s[n][1] = ex2f(s[n][1] - nm0);
            s[n][2] = ex2f(s[n][2] - nm1);
            s[n][3] = ex2f(s[n][3] - nm1);
            sum0 += s[n][0] + s[n][1];
            sum1 += s[n][2] + s[n][3];
        }
        sum0 += __shfl_xor_sync(0xffffffffu, sum0, 1);
        sum0 += __shfl_xor_sync(0xffffffffu, sum0, 2);
        sum1 += __shfl_xor_sync(0xffffffffu, sum1, 1);
        sum1 += __shfl_xor_sync(0xffffffffu, sum1, 2);
        li[0] = li[0] * al0 + sum0;
        li[1] = li[1] * al1 + sum1;

#pragma unroll
        for (int n = 0; n < 8; n++) {
            oacc[n][0] *= al0; oacc[n][1] *= al0;
            oacc[n][2] *= al1; oacc[n][3] *= al1;
        }

        // ---- P (hi) + O += P V (2-term: Vh + Vl) ----
#pragma unroll
        for (int kk = 0; kk < 4; kk++) {
            float* pA = s[2 * kk];
            float* pB = s[2 * kk + 1];
            uint32_t ph[4];
            ph[0] = packh(pA[0], pA[1]);
            ph[1] = packh(pA[2], pA[3]);
            ph[2] = packh(pB[0], pB[1]);
            ph[3] = packh(pB[2], pB[3]);
#pragma unroll
            for (int np = 0; np < 4; np++) {
                uint32_t vh0, vh1, vh2, vh3, vl0, vl1, vl2, vl3;
                const int row = kk * 16 + (sub & 1) * 8 + r8;
                const int ch = np * 2 + (sub >> 1);
                const uint32_t off = row * 128 + ((ch ^ (row & 7)) << 4);
                ldm_x4t(vh0, vh1, vh2, vh3, Vb + off);
                ldm_x4t(vl0, vl1, vl2, vl3, Vlb + off);
                uint32_t bh0[2] = {vh0, vh1}, bh1[2] = {vh2, vh3};
                uint32_t bl0[2] = {vl0, vl1}, bl1[2] = {vl2, vl3};
                mma_f16(oacc[np * 2], ph, bh0);
                mma_f16(oacc[np * 2], ph, bl0);
                mma_f16(oacc[np * 2 + 1], ph, bh1);
                mma_f16(oacc[np * 2 + 1], ph, bl1);
            }
        }
    }

    // ---- epilogue: O / li -> fp16 hi ----
    const float inv0 = 1.0f / li[0], inv1 = 1.0f / li[1];
#pragma unroll
    for (int n = 0; n < 8; n++) {
        const int col = h * DK + n * 8 + (lane & 3) * 2;
#pragma unroll
        for (int half = 0; half < 2; half++) {
            const float inv = half ? inv1 : inv0;
            const int row = b * SS + q0 + warp * 16 + (lane >> 2) + half * 8;
            const float a0 = oacc[n][half * 2 + 0] * inv;
            const float a1 = oacc[n][half * 2 + 1] * inv;
            *(__half2*)(oh + (size_t)row * DD + col) = __floats2half2_rn(a0, a1);
        }
    }
}

// ---------------------------------------------------------------------------
extern "C" void kernel_launch(void* const* d_in, const int* in_sizes, int n_in,
                              void* d_out, int out_size)
{
    const float* x  = (const float*)d_in[0];
    const float* rc = (const float*)d_in[1];
    const float* rs = (const float*)d_in[2];
    // d_in[3] = mask (causal; handled analytically)
    float* out = (float*)d_out;

    __half *xh, *qh, *kh, *vh, *vl, *oh, *wh, *wl;
    cudaGetSymbolAddress((void**)&xh, g_xh);
    cudaGetSymbolAddress((void**)&qh, g_qh);
    cudaGetSymbolAddress((void**)&kh, g_kh);
    cudaGetSymbolAddress((void**)&vh, g_vh);
    cudaGetSymbolAddress((void**)&vl, g_vl);
    cudaGetSymbolAddress((void**)&oh, g_oh);
    cudaGetSymbolAddress((void**)&wh, g_wh);
    cudaGetSymbolAddress((void**)&wl, g_wl);

    cudaFuncSetAttribute(gemm_mma_kernel,
                         cudaFuncAttributeMaxDynamicSharedMemorySize, GEMM_SMEM);
    cudaFuncSetAttribute(flash_tc_kernel,
                         cudaFuncAttributeMaxDynamicSharedMemorySize, FLASH_SMEM);

    // 1) converts/splits: x -> hi; 4 weights -> hi/lo (one fused launch)
    cvt_kernel<<<(MM * DD / 4 + 255) / 256, 256>>>((const float4*)x, xh, MM * DD / 4);
    WSplitArgs ws{};
    ws.src[0] = (const float4*)d_in[4];
    ws.src[1] = (const float4*)d_in[5];
    ws.src[2] = (const float4*)d_in[6];
    ws.src[3] = (const float4*)d_in[7];
    ws.hi = wh; ws.lo = wl;
    wsplit_kernel<<<dim3(DD * DD / 4 / 256, 4), 256>>>(ws);

    // 2) fused QKV projections (+RoPE on Q,K); Q,K 1-term, V 2-term
    GemmArgs aq{};
    aq.Ah = xh;
    aq.Wh[0] = wh;                   aq.Wl[0] = wl;
    aq.Wh[1] = wh + (size_t)DD*DD;   aq.Wl[1] = wl + (size_t)DD*DD;
    aq.Wh[2] = wh + (size_t)2*DD*DD; aq.Wl[2] = wl + (size_t)2*DD*DD;
    aq.Ch[0] = qh; aq.Cl[0] = qh;    // Q: nt=1, no lo written
    aq.Ch[1] = kh; aq.Cl[1] = kh;
    aq.Ch[2] = vh; aq.Cl[2] = vl;
    aq.Cf = nullptr;
    aq.rc = rc; aq.rs = rs; aq.nz_rope = 2; aq.out_half = 1;
    aq.nt[0] = 1; aq.nt[1] = 1; aq.nt[2] = 2;
    gemm_mma_kernel<<<dim3(DD / 128, MM / 128, 3), 256, GEMM_SMEM>>>(aq);

    // 3) tensor-core flash attention
    flash_tc_kernel<<<dim3(SS / 128, BB * HH), 256, FLASH_SMEM>>>(
        qh, kh, vh, vl, oh);

    // 4) output projection (2-term, fp32 out)
    GemmArgs ao{};
    ao.Ah = oh;
    ao.Wh[0] = wh + (size_t)3*DD*DD; ao.Wl[0] = wl + (size_t)3*DD*DD;
    ao.Wh[1] = ao.Wh[0]; ao.Wh[2] = ao.Wh[0];
    ao.Wl[1] = ao.Wl[0]; ao.Wl[2] = ao.Wl[0];
    ao.Cf = out;
    ao.rc = rc; ao.rs = rs; ao.nz_rope = 0; ao.out_half = 0;
    ao.nt[0] = 2; ao.nt[1] = 2; ao.nt[2] = 2;
    gemm_mma_kernel<<<dim3(DD / 128, MM / 128, 1), 256, GEMM_SMEM>>>(ao);
}

// round 8
// speedup vs baseline: 7.1156x; 1.5619x over previous
#include <cuda_runtime.h>
#include <cuda_fp16.h>
#include <math.h>
#include <cstdint>

// Problem constants
#define BB 2
#define SS 2048
#define DD 1024
#define HH 16
#define DK 64
#define MM (BB * SS)   // 4096

// Scratch (device globals: allocation rules forbid cudaMalloc)
__device__ __half g_xh[MM * DD];
__device__ __half g_qh[MM * DD];
__device__ __half g_kh[MM * DD];
__device__ __half g_vh[MM * DD];
__device__ __half g_oh[MM * DD];
__device__ __half g_wh[4][DD * DD];

// ---------------------------------------------------------------------------
// Helpers (sm_80-baseline PTX: ldmatrix / mma.sync / cp.async)
// ---------------------------------------------------------------------------
__device__ __forceinline__ uint32_t smem_u32(const void* p) {
    uint32_t a;
    asm("{ .reg .u64 t; cvta.to.shared.u64 t, %1; cvt.u32.u64 %0, t; }" : "=r"(a) : "l"(p));
    return a;
}
__device__ __forceinline__ void cpa16(uint32_t s, const void* g) {
    asm volatile("cp.async.cg.shared.global [%0], [%1], 16;" :: "r"(s), "l"(g));
}
#define CP_COMMIT() asm volatile("cp.async.commit_group;")
#define CP_WAIT(n)  asm volatile("cp.async.wait_group %0;" :: "n"(n))

__device__ __forceinline__ void ldm_x4(uint32_t& r0, uint32_t& r1, uint32_t& r2,
                                       uint32_t& r3, uint32_t addr) {
    asm volatile("ldmatrix.sync.aligned.m8n8.x4.shared.b16 {%0,%1,%2,%3}, [%4];"
                 : "=r"(r0), "=r"(r1), "=r"(r2), "=r"(r3) : "r"(addr));
}
__device__ __forceinline__ void ldm_x4t(uint32_t& r0, uint32_t& r1, uint32_t& r2,
                                        uint32_t& r3, uint32_t addr) {
    asm volatile("ldmatrix.sync.aligned.m8n8.x4.trans.shared.b16 {%0,%1,%2,%3}, [%4];"
                 : "=r"(r0), "=r"(r1), "=r"(r2), "=r"(r3) : "r"(addr));
}
__device__ __forceinline__ void mma_f16(float* d, const uint32_t* a, const uint32_t* b) {
    asm volatile(
        "mma.sync.aligned.m16n8k16.row.col.f32.f16.f16.f32 "
        "{%0,%1,%2,%3}, {%4,%5,%6,%7}, {%8,%9}, {%0,%1,%2,%3};"
        : "+f"(d[0]), "+f"(d[1]), "+f"(d[2]), "+f"(d[3])
        : "r"(a[0]), "r"(a[1]), "r"(a[2]), "r"(a[3]), "r"(b[0]), "r"(b[1]));
}
__device__ __forceinline__ float ex2f(float x) {
    float r;
    asm("ex2.approx.f32 %0, %1;" : "=f"(r) : "f"(x));
    return r;
}
__device__ __forceinline__ uint32_t packh(float a, float b) {
    __half2 t = __floats2half2_rn(a, b);
    return *(uint32_t*)&t;
}

// ---------------------------------------------------------------------------
// Convert fp32 -> fp16
// ---------------------------------------------------------------------------
__global__ __launch_bounds__(256)
void cvt_kernel(const float4* __restrict__ src, __half* __restrict__ hi, int n4)
{
    int i = blockIdx.x * 256 + threadIdx.x;
    if (i < n4) {
        float4 s = src[i];
        *(__half2*)(hi + 4 * (size_t)i)     = __floats2half2_rn(s.x, s.y);
        *(__half2*)(hi + 4 * (size_t)i + 2) = __floats2half2_rn(s.z, s.w);
    }
}

// Fused 4-weight convert: grid (DD*DD/4/256, 4)
struct WCvtArgs { const float4* src[4]; __half* hi; };
__global__ __launch_bounds__(256)
void wcvt_kernel(WCvtArgs a)
{
    const int w = blockIdx.y;
    const int i = blockIdx.x * 256 + threadIdx.x;
    float4 s = a.src[w][i];
    __half* hi = a.hi + (size_t)w * DD * DD + 4 * (size_t)i;
    *(__half2*)(hi)     = __floats2half2_rn(s.x, s.y);
    *(__half2*)(hi + 2) = __floats2half2_rn(s.z, s.w);
}

// ---------------------------------------------------------------------------
// mma.sync fp16 GEMM: C[m,n] = sum_k A[m,k]*W[n,k] (both K-major, hi only).
// 128x128 tile, BK=64 (one 128B row = 64 halves), 8 warps (4m x 2n),
// 3-stage cp.async pipeline. Epilogue: optional RoPE + per-z scale;
// out fp32 (Cf) or fp16 (Ch[z]).
// ---------------------------------------------------------------------------
struct GemmArgs {
    const __half* Ah;
    const __half* Wh[3];
    __half* Ch[3];
    float* Cf;
    const float* rc; const float* rs;
    int nz_rope; int out_half;
    float oscale[3];
};

#define TILE_BYTES 16384            // 128 rows x 128B (64 halves = BK)
#define STAGE_BYTES (2 * TILE_BYTES)
#define GEMM_SMEM (3 * STAGE_BYTES) // 98304
#define NCH (DD / 64)               // 16 K-chunks

__global__ __launch_bounds__(256)
void gemm_mma_kernel(GemmArgs p)
{
    extern __shared__ char smem[];
    const uint32_t sb = smem_u32(smem);
    const int tid = threadIdx.x;
    const int lane = tid & 31, wid = tid >> 5;
    const int warp_m = wid & 3, warp_n = wid >> 2;
    const int z = blockIdx.z;
    const int n0 = blockIdx.x * 128, m0 = blockIdx.y * 128;

    const __half* srcA = p.Ah + (size_t)m0 * DD;
    const __half* srcW = p.Wh[z] + (size_t)n0 * DD;

    auto load_chunk = [&](int c, int st) {
        const uint32_t sbase = sb + st * STAGE_BYTES;
#pragma unroll
        for (int i = 0; i < 4; i++) {
            const int t = tid + i * 256;       // 0..1023
            const int row = t >> 3, ch = t & 7;
            cpa16(sbase + row * 128 + ((ch ^ (row & 7)) << 4),
                  srcA + (size_t)row * DD + c * 64 + ch * 8);
        }
#pragma unroll
        for (int i = 0; i < 4; i++) {
            const int t = tid + i * 256;
            const int row = t >> 3, ch = t & 7;
            cpa16(sbase + TILE_BYTES + row * 128 + ((ch ^ (row & 7)) << 4),
                  srcW + (size_t)row * DD + c * 64 + ch * 8);
        }
    };

    float acc[2][8][4];
#pragma unroll
    for (int m = 0; m < 2; m++)
#pragma unroll
        for (int n = 0; n < 8; n++)
#pragma unroll
            for (int j = 0; j < 4; j++) acc[m][n][j] = 0.f;

    load_chunk(0, 0); CP_COMMIT();
    load_chunk(1, 1); CP_COMMIT();

    const int sub = lane >> 3, r8 = lane & 7;

    for (int c = 0; c < NCH; c++) {
        __syncthreads();
        if (c + 2 < NCH) load_chunk(c + 2, (c + 2) % 3);
        CP_COMMIT();
        CP_WAIT(2);
        __syncthreads();

        const uint32_t Ab = sb + (c % 3) * STAGE_BYTES;
        const uint32_t Wb = Ab + TILE_BYTES;

#pragma unroll
        for (int ka = 0; ka < 4; ka++) {
            uint32_t afh[2][4];
#pragma unroll
            for (int m = 0; m < 2; m++) {
                const int row = warp_m * 32 + m * 16 + (sub & 1) * 8 + r8;
                const int ch = ka * 2 + (sub >> 1);
                ldm_x4(afh[m][0], afh[m][1], afh[m][2], afh[m][3],
                       Ab + row * 128 + ((ch ^ (row & 7)) << 4));
            }
            uint32_t bfh[8][2];
#pragma unroll
            for (int np = 0; np < 4; np++) {
                const int row = warp_n * 64 + np * 16 + (sub >> 1) * 8 + r8;
                const int ch = ka * 2 + (sub & 1);
                uint32_t r0, r1, r2, r3;
                ldm_x4(r0, r1, r2, r3, Wb + row * 128 + ((ch ^ (row & 7)) << 4));
                bfh[np * 2][0] = r0;     bfh[np * 2][1] = r1;
                bfh[np * 2 + 1][0] = r2; bfh[np * 2 + 1][1] = r3;
            }
#pragma unroll
            for (int m = 0; m < 2; m++)
#pragma unroll
                for (int n = 0; n < 8; n++)
                    mma_f16(acc[m][n], afh[m], bfh[n]);
        }
    }

    const bool rope = (z < p.nz_rope);
    const float osc = p.oscale[z];
    const int lane4 = lane >> 2, lanem = lane & 3;
#pragma unroll
    for (int m = 0; m < 2; m++)
#pragma unroll
        for (int n = 0; n < 8; n++) {
            const int col = n0 + warp_n * 64 + n * 8 + lanem * 2;
#pragma unroll
            for (int half = 0; half < 2; half++) {
                const int row = m0 + warp_m * 32 + m * 16 + lane4 + half * 8;
                float a0 = acc[m][n][half * 2 + 0];
                float a1 = acc[m][n][half * 2 + 1];
                if (rope) {
                    const int s = row & (SS - 1);
                    const int pi = (col & (DK - 1)) >> 1;
                    const float cc = p.rc[s * (DK / 2) + pi];
                    const float sn = p.rs[s * (DK / 2) + pi];
                    const float t0 = a0 * cc - a1 * sn;
                    const float t1 = a0 * sn + a1 * cc;
                    a0 = t0; a1 = t1;
                }
                a0 *= osc; a1 *= osc;
                if (p.out_half) {
                    *(__half2*)(p.Ch[z] + (size_t)row * DD + col) =
                        __floats2half2_rn(a0, a1);
                } else {
                    *(float2*)(p.Cf + (size_t)row * DD + col) = make_float2(a0, a1);
                }
            }
        }
}

// ---------------------------------------------------------------------------
// Tensor-core flash attention (causal), plain fp16.
// Q pre-scaled by log2(e)/64 in the Q projection -> S is base-2 logits.
// QK^T: 1 term.  PV: 1 term.
// Q tile 128 rows, KV steps 64, 8 warps, 256 threads.
// Smem: Qh[128][64] + 2 stages of {Kh,Vh}[64][64], 128B swizzled rows.
// ---------------------------------------------------------------------------
#define FQ_BYTES 16384              // 128 rows * 128B
#define FKV_TILE 8192               // 64 rows * 128B
#define FSTAGE (2 * FKV_TILE)       // 16384
#define FLASH_SMEM (FQ_BYTES + 2 * FSTAGE)   // 49152

__global__ __launch_bounds__(256)
void flash_tc_kernel(const __half* __restrict__ qh,
                     const __half* __restrict__ kh,
                     const __half* __restrict__ vh,
                     __half* __restrict__ oh)
{
    extern __shared__ char smem[];
    const uint32_t sb = smem_u32(smem);
    const int tid = threadIdx.x;
    const int lane = tid & 31, warp = tid >> 5;
    const int sub = lane >> 3, r8 = lane & 7;
    const int qtile = (int)gridDim.x - 1 - (int)blockIdx.x;   // heavy tiles first
    const int bh = blockIdx.y;
    const int b = bh / HH, h = bh % HH;
    const int q0 = qtile * 128;
    const int njt = 2 * qtile + 2;
    const size_t gbase = (size_t)b * SS * DD + h * DK;

    const __half* kvsrc[2] = {kh + gbase, vh + gbase};

#pragma unroll
    for (int i = 0; i < 4; i++) {
        const int s = tid + i * 256;
        const int row = s >> 3, ch = s & 7;
        cpa16(sb + row * 128 + ((ch ^ (row & 7)) << 4),
              qh + gbase + (size_t)(q0 + row) * DD + ch * 8);
    }
    auto load_kv = [&](int jt, int st) {
        const int k0 = jt * 64;
#pragma unroll
        for (int i = 0; i < 4; i++) {
            const int s = tid + i * 256;     // 0..1023
            const int tile = s >> 9;         // Kh, Vh
            const int t = s & 511;
            const int row = t >> 3, ch = t & 7;
            cpa16(sb + FQ_BYTES + st * FSTAGE + tile * FKV_TILE +
                      row * 128 + ((ch ^ (row & 7)) << 4),
                  kvsrc[tile] + (size_t)(k0 + row) * DD + ch * 8);
        }
    };
    load_kv(0, 0);
    CP_COMMIT();
    CP_WAIT(0);
    __syncthreads();

    uint32_t qfr[4][4];
#pragma unroll
    for (int ka = 0; ka < 4; ka++) {
        const int row = warp * 16 + (sub & 1) * 8 + r8;
        const int ch = ka * 2 + (sub >> 1);
        ldm_x4(qfr[ka][0], qfr[ka][1], qfr[ka][2], qfr[ka][3],
               sb + row * 128 + ((ch ^ (row & 7)) << 4));
    }

    float oacc[8][4];
#pragma unroll
    for (int n = 0; n < 8; n++)
#pragma unroll
        for (int j = 0; j < 4; j++) oacc[n][j] = 0.f;
    float mi[2] = {-INFINITY, -INFINITY};
    float li[2] = {0.f, 0.f};

    const int qrow0 = q0 + warp * 16 + (lane >> 2);

    for (int jt = 0; jt < njt; jt++) {
        const int buf = jt & 1;
        const int k0 = jt * 64;
        __syncthreads();
        if (jt + 1 < njt) { load_kv(jt + 1, 1 - buf); CP_COMMIT(); CP_WAIT(1); }
        else             { CP_WAIT(0); }
        __syncthreads();

        const uint32_t Kb = sb + FQ_BYTES + buf * FSTAGE;
        const uint32_t Vb = Kb + FKV_TILE;

        // ---- S = Q K^T (base-2 logits; Q pre-scaled) ----
        float s[8][4];
#pragma unroll
        for (int n = 0; n < 8; n++)
#pragma unroll
            for (int j = 0; j < 4; j++) s[n][j] = 0.f;

#pragma unroll
        for (int ka = 0; ka < 4; ka++) {
            uint32_t bfr[8][2];
#pragma unroll
            for (int np = 0; np < 4; np++) {
                const int row = np * 16 + (sub >> 1) * 8 + r8;
                const int ch = ka * 2 + (sub & 1);
                uint32_t r0, r1, r2, r3;
                ldm_x4(r0, r1, r2, r3, Kb + row * 128 + ((ch ^ (row & 7)) << 4));
                bfr[np * 2][0] = r0;     bfr[np * 2][1] = r1;
                bfr[np * 2 + 1][0] = r2; bfr[np * 2 + 1][1] = r3;
            }
#pragma unroll
            for (int n = 0; n < 8; n++)
                mma_f16(s[n], qfr[ka], bfr[n]);
        }

        // ---- causal mask (diagonal steps only) ----
        if (k0 + 64 > qrow0) {
#pragma unroll
            for (int n = 0; n < 8; n++) {
                const int col = k0 + n * 8 + (lane & 3) * 2;
#pragma unroll
                for (int j = 0; j < 4; j++) {
                    const int kv = col + (j & 1);
                    const int qr = qrow0 + (j >> 1) * 8;
                    if (kv > qr) s[n][j] = -1e30f;
                }
            }
        }

        // ---- online softmax (skip rescale when max unchanged) ----
        float mx0 = s[0][0], mx1 = s[0][2];
#pragma unroll
        for (int n = 0; n < 8; n++) {
            mx0 = fmaxf(mx0, fmaxf(s[n][0], s[n][1]));
            mx1 = fmaxf(mx1, fmaxf(s[n][2], s[n][3]));
        }
        mx0 = fmaxf(mx0, __shfl_xor_sync(0xffffffffu, mx0, 1));
        mx0 = fmaxf(mx0, __shfl_xor_sync(0xffffffffu, mx0, 2));
        mx1 = fmaxf(mx1, __shfl_xor_sync(0xffffffffu, mx1, 1));
        mx1 = fmaxf(mx1, __shfl_xor_sync(0xffffffffu, mx1, 2));

        if (mx0 > mi[0] || mx1 > mi[1]) {
            const float nm0 = fmaxf(mi[0], mx0), nm1 = fmaxf(mi[1], mx1);
            const float al0 = ex2f(mi[0] - nm0), al1 = ex2f(mi[1] - nm1);
            li[0] *= al0; li[1] *= al1;
#pragma unroll
            for (int n = 0; n < 8; n++) {
                oacc[n][0] *= al0; oacc[n][1] *= al0;
                oacc[n][2] *= al1; oacc[n][3] *= al1;
            }
            mi[0] = nm0; mi[1] = nm1;
        }

        float sum0 = 0.f, sum1 = 0.f;
#pragma unroll
        for (int n = 0; n < 8; n++) {
            s[n][0] = ex2f(s[n][0] - mi[0]);
            s[n][1] = ex2f(s[n][1] - mi[0]);
            s[n][2] = ex2f(s[n][2] - mi[1]);
            s[n][3] = ex2f(s[n][3] - mi[1]);
            sum0 += s[n][0] + s[n][1];
            sum1 += s[n][2] + s[n][3];
        }
        sum0 += __shfl_xor_sync(0xffffffffu, sum0, 1);
        sum0 += __shfl_xor_sync(0xffffffffu, sum0, 2);
        sum1 += __shfl_xor_sync(0xffffffffu, sum1, 1);
        sum1 += __shfl_xor_sync(0xffffffffu, sum1, 2);
        li[0] += sum0;
        li[1] += sum1;

        // ---- P (fp16) + O += P V (1 term) ----
#pragma unroll
        for (int kk = 0; kk < 4; kk++) {
            float* pA = s[2 * kk];
            float* pB = s[2 * kk + 1];
            uint32_t ph[4];
            ph[0] = packh(pA[0], pA[1]);
            ph[1] = packh(pA[2], pA[3]);
            ph[2] = packh(pB[0], pB[1]);
            ph[3] = packh(pB[2], pB[3]);
#pragma unroll
            for (int np = 0; np < 4; np++) {
                uint32_t v0, v1, v2, v3;
                const int row = kk * 16 + (sub & 1) * 8 + r8;
                const int ch = np * 2 + (sub >> 1);
                ldm_x4t(v0, v1, v2, v3, Vb + row * 128 + ((ch ^ (row & 7)) << 4));
                uint32_t b0[2] = {v0, v1}, b1[2] = {v2, v3};
                mma_f16(oacc[np * 2], ph, b0);
                mma_f16(oacc[np * 2 + 1], ph, b1);
            }
        }
    }

    // ---- epilogue: O / li -> fp16 ----
    const float inv0 = 1.0f / li[0], inv1 = 1.0f / li[1];
#pragma unroll
    for (int n = 0; n < 8; n++) {
        const int col = h * DK + n * 8 + (lane & 3) * 2;
#pragma unroll
        for (int half = 0; half < 2; half++) {
            const float inv = half ? inv1 : inv0;
            const int row = b * SS + q0 + warp * 16 + (lane >> 2) + half * 8;
            const float a0 = oacc[n][half * 2 + 0] * inv;
            const float a1 = oacc[n][half * 2 + 1] * inv;
            *(__half2*)(oh + (size_t)row * DD + col) = __floats2half2_rn(a0, a1);
        }
    }
}

// ---------------------------------------------------------------------------
extern "C" void kernel_launch(void* const* d_in, const int* in_sizes, int n_in,
                              void* d_out, int out_size)
{
    const float* x  = (const float*)d_in[0];
    const float* rc = (const float*)d_in[1];
    const float* rs = (const float*)d_in[2];
    // d_in[3] = mask (causal; handled analytically)
    float* out = (float*)d_out;

    __half *xh, *qh, *kh, *vh, *oh, *wh;
    cudaGetSymbolAddress((void**)&xh, g_xh);
    cudaGetSymbolAddress((void**)&qh, g_qh);
    cudaGetSymbolAddress((void**)&kh, g_kh);
    cudaGetSymbolAddress((void**)&vh, g_vh);
    cudaGetSymbolAddress((void**)&oh, g_oh);
    cudaGetSymbolAddress((void**)&wh, g_wh);

    cudaFuncSetAttribute(gemm_mma_kernel,
                         cudaFuncAttributeMaxDynamicSharedMemorySize, GEMM_SMEM);
    cudaFuncSetAttribute(flash_tc_kernel,
                         cudaFuncAttributeMaxDynamicSharedMemorySize, FLASH_SMEM);

    // 1) converts: x and 4 weights -> fp16
    cvt_kernel<<<(MM * DD / 4 + 255) / 256, 256>>>((const float4*)x, xh, MM * DD / 4);
    WCvtArgs wc{};
    wc.src[0] = (const float4*)d_in[4];
    wc.src[1] = (const float4*)d_in[5];
    wc.src[2] = (const float4*)d_in[6];
    wc.src[3] = (const float4*)d_in[7];
    wc.hi = wh;
    wcvt_kernel<<<dim3(DD * DD / 4 / 256, 4), 256>>>(wc);

    // 2) fused QKV projections (+RoPE on Q,K; Q scaled by log2e/64)
    const float C2 = 1.4426950408889634f / 64.0f;
    GemmArgs aq{};
    aq.Ah = xh;
    aq.Wh[0] = wh;
    aq.Wh[1] = wh + (size_t)DD * DD;
    aq.Wh[2] = wh + (size_t)2 * DD * DD;
    aq.Ch[0] = qh; aq.Ch[1] = kh; aq.Ch[2] = vh;
    aq.Cf = nullptr;
    aq.rc = rc; aq.rs = rs; aq.nz_rope = 2; aq.out_half = 1;
    aq.oscale[0] = C2; aq.oscale[1] = 1.f; aq.oscale[2] = 1.f;
    gemm_mma_kernel<<<dim3(DD / 128, MM / 128, 3), 256, GEMM_SMEM>>>(aq);

    // 3) tensor-core flash attention
    flash_tc_kernel<<<dim3(SS / 128, BB * HH), 256, FLASH_SMEM>>>(qh, kh, vh, oh);

    // 4) output projection (fp32 out)
    GemmArgs ao{};
    ao.Ah = oh;
    ao.Wh[0] = wh + (size_t)3 * DD * DD;
    ao.Wh[1] = ao.Wh[0]; ao.Wh[2] = ao.Wh[0];
    ao.Cf = out;
    ao.rc = rc; ao.rs = rs; ao.nz_rope = 0; ao.out_half = 0;
    ao.oscale[0] = 1.f; ao.oscale[1] = 1.f; ao.oscale[2] = 1.f;
    gemm_mma_kernel<<<dim3(DD / 128, MM / 128, 1), 256, GEMM_SMEM>>>(ao);
}

// round 9
// speedup vs baseline: 7.3579x; 1.0340x over previous
#include <cuda_runtime.h>
#include <cuda_fp16.h>
#include <math.h>
#include <cstdint>

// Problem constants
#define BB 2
#define SS 2048
#define DD 1024
#define HH 16
#define DK 64
#define MM (BB * SS)   // 4096

// Scratch (device globals: allocation rules forbid cudaMalloc)
__device__ __half g_xh[MM * DD];
__device__ __half g_qh[MM * DD];
__device__ __half g_kh[MM * DD];
__device__ __half g_vh[MM * DD];
__device__ __half g_oh[MM * DD];
__device__ __half g_wh[4][DD * DD];

// ---------------------------------------------------------------------------
// Helpers (sm_80-baseline PTX: ldmatrix / mma.sync / cp.async)
// ---------------------------------------------------------------------------
__device__ __forceinline__ uint32_t smem_u32(const void* p) {
    uint32_t a;
    asm("{ .reg .u64 t; cvta.to.shared.u64 t, %1; cvt.u32.u64 %0, t; }" : "=r"(a) : "l"(p));
    return a;
}
__device__ __forceinline__ void cpa16(uint32_t s, const void* g) {
    asm volatile("cp.async.cg.shared.global [%0], [%1], 16;" :: "r"(s), "l"(g));
}
#define CP_COMMIT() asm volatile("cp.async.commit_group;")
#define CP_WAIT(n)  asm volatile("cp.async.wait_group %0;" :: "n"(n))

__device__ __forceinline__ void ldm_x4(uint32_t& r0, uint32_t& r1, uint32_t& r2,
                                       uint32_t& r3, uint32_t addr) {
    asm volatile("ldmatrix.sync.aligned.m8n8.x4.shared.b16 {%0,%1,%2,%3}, [%4];"
                 : "=r"(r0), "=r"(r1), "=r"(r2), "=r"(r3) : "r"(addr));
}
__device__ __forceinline__ void ldm_x4t(uint32_t& r0, uint32_t& r1, uint32_t& r2,
                                        uint32_t& r3, uint32_t addr) {
    asm volatile("ldmatrix.sync.aligned.m8n8.x4.trans.shared.b16 {%0,%1,%2,%3}, [%4];"
                 : "=r"(r0), "=r"(r1), "=r"(r2), "=r"(r3) : "r"(addr));
}
__device__ __forceinline__ void mma_f16(float* d, const uint32_t* a, const uint32_t* b) {
    asm volatile(
        "mma.sync.aligned.m16n8k16.row.col.f32.f16.f16.f32 "
        "{%0,%1,%2,%3}, {%4,%5,%6,%7}, {%8,%9}, {%0,%1,%2,%3};"
        : "+f"(d[0]), "+f"(d[1]), "+f"(d[2]), "+f"(d[3])
        : "r"(a[0]), "r"(a[1]), "r"(a[2]), "r"(a[3]), "r"(b[0]), "r"(b[1]));
}
__device__ __forceinline__ float ex2f(float x) {
    float r;
    asm("ex2.approx.f32 %0, %1;" : "=f"(r) : "f"(x));
    return r;
}
__device__ __forceinline__ uint32_t packh(float a, float b) {
    __half2 t = __floats2half2_rn(a, b);
    return *(uint32_t*)&t;
}

// ---------------------------------------------------------------------------
// Fused convert: x (4096 blocks) + 4 weights (1024 blocks each) -> fp16.
// Flat grid of 8192 blocks x 256 threads.
// ---------------------------------------------------------------------------
struct CvtArgs { const float4* x; const float4* w[4]; __half* xh; __half* wh; };

#define X_BLOCKS (MM * DD / 4 / 256)       // 4096
#define W_BLOCKS (DD * DD / 4 / 256)       // 1024

__global__ __launch_bounds__(256)
void cvt_all_kernel(CvtArgs a)
{
    const int bid = blockIdx.x;
    if (bid < X_BLOCKS) {
        const int i = bid * 256 + threadIdx.x;
        float4 s = a.x[i];
        __half* hi = a.xh + 4 * (size_t)i;
        *(__half2*)(hi)     = __floats2half2_rn(s.x, s.y);
        *(__half2*)(hi + 2) = __floats2half2_rn(s.z, s.w);
    } else {
        const int r = bid - X_BLOCKS;
        const int w = r >> 10;                       // /W_BLOCKS
        const int i = (r & (W_BLOCKS - 1)) * 256 + threadIdx.x;
        float4 s = a.w[w][i];
        __half* hi = a.wh + (size_t)w * DD * DD + 4 * (size_t)i;
        *(__half2*)(hi)     = __floats2half2_rn(s.x, s.y);
        *(__half2*)(hi + 2) = __floats2half2_rn(s.z, s.w);
    }
}

// ---------------------------------------------------------------------------
// mma.sync fp16 GEMM: C[m,n] = sum_k A[m,k]*W[n,k] (both K-major).
// 128x128 tile, BK=64 (one 128B row), 8 warps (4m x 2n), 3-stage cp.async
// pipeline (prefetch-2, two syncs -- latency-safe). Epilogue: optional RoPE +
// per-z scale; out fp32 (Cf) or fp16 (Ch[z]).
// ---------------------------------------------------------------------------
struct GemmArgs {
    const __half* Ah;
    const __half* Wh[3];
    __half* Ch[3];
    float* Cf;
    const float* rc; const float* rs;
    int nz_rope; int out_half;
    float oscale[3];
};

#define TILE_BYTES 16384            // 128 rows x 128B (64 halves = BK)
#define STAGE_BYTES (2 * TILE_BYTES)
#define GEMM_SMEM (3 * STAGE_BYTES) // 98304
#define NCH (DD / 64)               // 16 K-chunks

__global__ __launch_bounds__(256)
void gemm_mma_kernel(GemmArgs p)
{
    extern __shared__ char smem[];
    const uint32_t sb = smem_u32(smem);
    const int tid = threadIdx.x;
    const int lane = tid & 31, wid = tid >> 5;
    const int warp_m = wid & 3, warp_n = wid >> 2;
    const int z = blockIdx.z;
    const int n0 = blockIdx.x * 128, m0 = blockIdx.y * 128;

    const __half* srcA = p.Ah + (size_t)m0 * DD;
    const __half* srcW = p.Wh[z] + (size_t)n0 * DD;

    auto load_chunk = [&](int c, int st) {
        const uint32_t sbase = sb + st * STAGE_BYTES;
#pragma unroll
        for (int i = 0; i < 4; i++) {
            const int t = tid + i * 256;       // 0..1023
            const int row = t >> 3, ch = t & 7;
            cpa16(sbase + row * 128 + ((ch ^ (row & 7)) << 4),
                  srcA + (size_t)row * DD + c * 64 + ch * 8);
        }
#pragma unroll
        for (int i = 0; i < 4; i++) {
            const int t = tid + i * 256;
            const int row = t >> 3, ch = t & 7;
            cpa16(sbase + TILE_BYTES + row * 128 + ((ch ^ (row & 7)) << 4),
                  srcW + (size_t)row * DD + c * 64 + ch * 8);
        }
    };

    float acc[2][8][4];
#pragma unroll
    for (int m = 0; m < 2; m++)
#pragma unroll
        for (int n = 0; n < 8; n++)
#pragma unroll
            for (int j = 0; j < 4; j++) acc[m][n][j] = 0.f;

    load_chunk(0, 0); CP_COMMIT();
    load_chunk(1, 1); CP_COMMIT();

    const int sub = lane >> 3, r8 = lane & 7;

    for (int c = 0; c < NCH; c++) {
        __syncthreads();
        if (c + 2 < NCH) load_chunk(c + 2, (c + 2) % 3);
        CP_COMMIT();
        CP_WAIT(2);
        __syncthreads();

        const uint32_t Ab = sb + (c % 3) * STAGE_BYTES;
        const uint32_t Wb = Ab + TILE_BYTES;

#pragma unroll
        for (int ka = 0; ka < 4; ka++) {
            uint32_t afh[2][4];
#pragma unroll
            for (int m = 0; m < 2; m++) {
                const int row = warp_m * 32 + m * 16 + (sub & 1) * 8 + r8;
                const int ch = ka * 2 + (sub >> 1);
                ldm_x4(afh[m][0], afh[m][1], afh[m][2], afh[m][3],
                       Ab + row * 128 + ((ch ^ (row & 7)) << 4));
            }
            uint32_t bfh[8][2];
#pragma unroll
            for (int np = 0; np < 4; np++) {
                const int row = warp_n * 64 + np * 16 + (sub >> 1) * 8 + r8;
                const int ch = ka * 2 + (sub & 1);
                uint32_t r0, r1, r2, r3;
                ldm_x4(r0, r1, r2, r3, Wb + row * 128 + ((ch ^ (row & 7)) << 4));
                bfh[np * 2][0] = r0;     bfh[np * 2][1] = r1;
                bfh[np * 2 + 1][0] = r2; bfh[np * 2 + 1][1] = r3;
            }
#pragma unroll
            for (int m = 0; m < 2; m++)
#pragma unroll
                for (int n = 0; n < 8; n++)
                    mma_f16(acc[m][n], afh[m], bfh[n]);
        }
    }

    const bool rope = (z < p.nz_rope);
    const float osc = p.oscale[z];
    const int lane4 = lane >> 2, lanem = lane & 3;
#pragma unroll
    for (int m = 0; m < 2; m++)
#pragma unroll
        for (int n = 0; n < 8; n++) {
            const int col = n0 + warp_n * 64 + n * 8 + lanem * 2;
#pragma unroll
            for (int half = 0; half < 2; half++) {
                const int row = m0 + warp_m * 32 + m * 16 + lane4 + half * 8;
                float a0 = acc[m][n][half * 2 + 0];
                float a1 = acc[m][n][half * 2 + 1];
                if (rope) {
                    const int s = row & (SS - 1);
                    const int pi = (col & (DK - 1)) >> 1;
                    const float cc = p.rc[s * (DK / 2) + pi];
                    const float sn = p.rs[s * (DK / 2) + pi];
                    const float t0 = a0 * cc - a1 * sn;
                    const float t1 = a0 * sn + a1 * cc;
                    a0 = t0; a1 = t1;
                }
                a0 *= osc; a1 *= osc;
                if (p.out_half) {
                    *(__half2*)(p.Ch[z] + (size_t)row * DD + col) =
                        __floats2half2_rn(a0, a1);
                } else {
                    *(float2*)(p.Cf + (size_t)row * DD + col) = make_float2(a0, a1);
                }
            }
        }
}

// ---------------------------------------------------------------------------
// Tensor-core flash attention (causal), plain fp16, Q pre-scaled by log2e/64.
// 3-stage KV pipeline, prefetch-1, ONE __syncthreads per KV step.
// Safety: load(jt+1) at iter jt (jt>=1) targets slot (jt+1)%3, last consumed
// at iter jt-2; every warp's consume(jt-2) precedes its arrival at sync(jt-1),
// and the load is issued only after passing sync(jt-1). Data-ready: wait(1)
// leaves only the just-issued group in flight.
// ---------------------------------------------------------------------------
#define FQ_BYTES 16384              // 128 rows * 128B
#define FKV_TILE 8192               // 64 rows * 128B
#define FSTAGE (2 * FKV_TILE)       // 16384 (Kh + Vh)
#define FLASH_SMEM (FQ_BYTES + 3 * FSTAGE)   // 65536

__global__ __launch_bounds__(256)
void flash_tc_kernel(const __half* __restrict__ qh,
                     const __half* __restrict__ kh,
                     const __half* __restrict__ vh,
                     __half* __restrict__ oh)
{
    extern __shared__ char smem[];
    const uint32_t sb = smem_u32(smem);
    const int tid = threadIdx.x;
    const int lane = tid & 31, warp = tid >> 5;
    const int sub = lane >> 3, r8 = lane & 7;
    const int qtile = (int)gridDim.x - 1 - (int)blockIdx.x;   // heavy tiles first
    const int bh = blockIdx.y;
    const int b = bh / HH, h = bh % HH;
    const int q0 = qtile * 128;
    const int njt = 2 * qtile + 2;   // always >= 2
    const size_t gbase = (size_t)b * SS * DD + h * DK;

    const __half* kvsrc[2] = {kh + gbase, vh + gbase};

    auto load_kv = [&](int jt, int st) {
        const int k0 = jt * 64;
#pragma unroll
        for (int i = 0; i < 4; i++) {
            const int s = tid + i * 256;     // 0..1023
            const int tile = s >> 9;         // Kh, Vh
            const int t = s & 511;
            const int row = t >> 3, ch = t & 7;
            cpa16(sb + FQ_BYTES + st * FSTAGE + tile * FKV_TILE +
                      row * 128 + ((ch ^ (row & 7)) << 4),
                  kvsrc[tile] + (size_t)(k0 + row) * DD + ch * 8);
        }
    };

    // prologue: group G0 = {Q tile, KV step 0}; group G1 = {KV step 1}
#pragma unroll
    for (int i = 0; i < 4; i++) {
        const int s = tid + i * 256;
        const int row = s >> 3, ch = s & 7;
        cpa16(sb + row * 128 + ((ch ^ (row & 7)) << 4),
              qh + gbase + (size_t)(q0 + row) * DD + ch * 8);
    }
    load_kv(0, 0);
    CP_COMMIT();
    load_kv(1, 1);
    CP_COMMIT();

    uint32_t qfr[4][4];
    float oacc[8][4];
#pragma unroll
    for (int n = 0; n < 8; n++)
#pragma unroll
        for (int j = 0; j < 4; j++) oacc[n][j] = 0.f;
    float mi[2] = {-INFINITY, -INFINITY};
    float li[2] = {0.f, 0.f};

    const int qrow0 = q0 + warp * 16 + (lane >> 2);

    for (int jt = 0; jt < njt; jt++) {
        if (jt >= 1 && jt + 1 < njt) { load_kv(jt + 1, (jt + 1) % 3); CP_COMMIT(); }
        if (jt + 1 < njt) { CP_WAIT(1); } else { CP_WAIT(0); }
        __syncthreads();

        if (jt == 0) {
            // Q fragments register-resident (Q ready with G0)
#pragma unroll
            for (int ka = 0; ka < 4; ka++) {
                const int row = warp * 16 + (sub & 1) * 8 + r8;
                const int ch = ka * 2 + (sub >> 1);
                ldm_x4(qfr[ka][0], qfr[ka][1], qfr[ka][2], qfr[ka][3],
                       sb + row * 128 + ((ch ^ (row & 7)) << 4));
            }
        }

        const int k0 = jt * 64;
        const uint32_t Kb = sb + FQ_BYTES + (jt % 3) * FSTAGE;
        const uint32_t Vb = Kb + FKV_TILE;

        // ---- S = Q K^T (base-2 logits; Q pre-scaled) ----
        float s[8][4];
#pragma unroll
        for (int n = 0; n < 8; n++)
#pragma unroll
            for (int j = 0; j < 4; j++) s[n][j] = 0.f;

#pragma unroll
        for (int ka = 0; ka < 4; ka++) {
            uint32_t bfr[8][2];
#pragma unroll
            for (int np = 0; np < 4; np++) {
                const int row = np * 16 + (sub >> 1) * 8 + r8;
                const int ch = ka * 2 + (sub & 1);
                uint32_t r0, r1, r2, r3;
                ldm_x4(r0, r1, r2, r3, Kb + row * 128 + ((ch ^ (row & 7)) << 4));
                bfr[np * 2][0] = r0;     bfr[np * 2][1] = r1;
                bfr[np * 2 + 1][0] = r2; bfr[np * 2 + 1][1] = r3;
            }
#pragma unroll
            for (int n = 0; n < 8; n++)
                mma_f16(s[n], qfr[ka], bfr[n]);
        }

        // ---- causal mask (diagonal steps only) ----
        if (k0 + 64 > qrow0) {
#pragma unroll
            for (int n = 0; n < 8; n++) {
                const int col = k0 + n * 8 + (lane & 3) * 2;
#pragma unroll
                for (int j = 0; j < 4; j++) {
                    const int kv = col + (j & 1);
                    const int qr = qrow0 + (j >> 1) * 8;
                    if (kv > qr) s[n][j] = -1e30f;
                }
            }
        }

        // ---- online softmax (skip rescale when max unchanged) ----
        float mx0 = s[0][0], mx1 = s[0][2];
#pragma unroll
        for (int n = 0; n < 8; n++) {
            mx0 = fmaxf(mx0, fmaxf(s[n][0], s[n][1]));
            mx1 = fmaxf(mx1, fmaxf(s[n][2], s[n][3]));
        }
        mx0 = fmaxf(mx0, __shfl_xor_sync(0xffffffffu, mx0, 1));
        mx0 = fmaxf(mx0, __shfl_xor_sync(0xffffffffu, mx0, 2));
        mx1 = fmaxf(mx1, __shfl_xor_sync(0xffffffffu, mx1, 1));
        mx1 = fmaxf(mx1, __shfl_xor_sync(0xffffffffu, mx1, 2));

        if (mx0 > mi[0] || mx1 > mi[1]) {
            const float nm0 = fmaxf(mi[0], mx0), nm1 = fmaxf(mi[1], mx1);
            const float al0 = ex2f(mi[0] - nm0), al1 = ex2f(mi[1] - nm1);
            li[0] *= al0; li[1] *= al1;
#pragma unroll
            for (int n = 0; n < 8; n++) {
                oacc[n][0] *= al0; oacc[n][1] *= al0;
                oacc[n][2] *= al1; oacc[n][3] *= al1;
            }
            mi[0] = nm0; mi[1] = nm1;
        }

        float sum0 = 0.f, sum1 = 0.f;
#pragma unroll
        for (int n = 0; n < 8; n++) {
            s[n][0] = ex2f(s[n][0] - mi[0]);
            s[n][1] = ex2f(s[n][1] - mi[0]);
            s[n][2] = ex2f(s[n][2] - mi[1]);
            s[n][3] = ex2f(s[n][3] - mi[1]);
            sum0 += s[n][0] + s[n][1];
            sum1 += s[n][2] + s[n][3];
        }
        sum0 += __shfl_xor_sync(0xffffffffu, sum0, 1);
        sum0 += __shfl_xor_sync(0xffffffffu, sum0, 2);
        sum1 += __shfl_xor_sync(0xffffffffu, sum1, 1);
        sum1 += __shfl_xor_sync(0xffffffffu, sum1, 2);
        li[0] += sum0;
        li[1] += sum1;

        // ---- P (fp16) + O += P V (1 term) ----
#pragma unroll
        for (int kk = 0; kk < 4; kk++) {
            float* pA = s[2 * kk];
            float* pB = s[2 * kk + 1];
            uint32_t ph[4];
            ph[0] = packh(pA[0], pA[1]);
            ph[1] = packh(pA[2], pA[3]);
            ph[2] = packh(pB[0], pB[1]);
            ph[3] = packh(pB[2], pB[3]);
#pragma unroll
            for (int np = 0; np < 4; np++) {
                uint32_t v0, v1, v2, v3;
                const int row = kk * 16 + (sub & 1) * 8 + r8;
                const int ch = np * 2 + (sub >> 1);
                ldm_x4t(v0, v1, v2, v3, Vb + row * 128 + ((ch ^ (row & 7)) << 4));
                uint32_t b0[2] = {v0, v1}, b1[2] = {v2, v3};
                mma_f16(oacc[np * 2], ph, b0);
                mma_f16(oacc[np * 2 + 1], ph, b1);
            }
        }
    }

    // ---- epilogue: O / li -> fp16 ----
    const float inv0 = 1.0f / li[0], inv1 = 1.0f / li[1];
#pragma unroll
    for (int n = 0; n < 8; n++) {
        const int col = h * DK + n * 8 + (lane & 3) * 2;
#pragma unroll
        for (int half = 0; half < 2; half++) {
            const float inv = half ? inv1 : inv0;
            const int row = b * SS + q0 + warp * 16 + (lane >> 2) + half * 8;
            const float a0 = oacc[n][half * 2 + 0] * inv;
            const float a1 = oacc[n][half * 2 + 1] * inv;
            *(__half2*)(oh + (size_t)row * DD + col) = __floats2half2_rn(a0, a1);
        }
    }
}

// ---------------------------------------------------------------------------
extern "C" void kernel_launch(void* const* d_in, const int* in_sizes, int n_in,
                              void* d_out, int out_size)
{
    const float* x  = (const float*)d_in[0];
    const float* rc = (const float*)d_in[1];
    const float* rs = (const float*)d_in[2];
    // d_in[3] = mask (causal; handled analytically)
    float* out = (float*)d_out;

    __half *xh, *qh, *kh, *vh, *oh, *wh;
    cudaGetSymbolAddress((void**)&xh, g_xh);
    cudaGetSymbolAddress((void**)&qh, g_qh);
    cudaGetSymbolAddress((void**)&kh, g_kh);
    cudaGetSymbolAddress((void**)&vh, g_vh);
    cudaGetSymbolAddress((void**)&oh, g_oh);
    cudaGetSymbolAddress((void**)&wh, g_wh);

    cudaFuncSetAttribute(gemm_mma_kernel,
                         cudaFuncAttributeMaxDynamicSharedMemorySize, GEMM_SMEM);
    cudaFuncSetAttribute(flash_tc_kernel,
                         cudaFuncAttributeMaxDynamicSharedMemorySize, FLASH_SMEM);

    // 1) single fused convert launch: x + 4 weights -> fp16
    CvtArgs ca{};
    ca.x = (const float4*)x;
    ca.w[0] = (const float4*)d_in[4];
    ca.w[1] = (const float4*)d_in[5];
    ca.w[2] = (const float4*)d_in[6];
    ca.w[3] = (const float4*)d_in[7];
    ca.xh = xh; ca.wh = wh;
    cvt_all_kernel<<<X_BLOCKS + 4 * W_BLOCKS, 256>>>(ca);

    // 2) fused QKV projections (+RoPE on Q,K; Q scaled by log2e/64)
    const float C2 = 1.4426950408889634f / 64.0f;
    GemmArgs aq{};
    aq.Ah = xh;
    aq.Wh[0] = wh;
    aq.Wh[1] = wh + (size_t)DD * DD;
    aq.Wh[2] = wh + (size_t)2 * DD * DD;
    aq.Ch[0] = qh; aq.Ch[1] = kh; aq.Ch[2] = vh;
    aq.Cf = nullptr;
    aq.rc = rc; aq.rs = rs; aq.nz_rope = 2; aq.out_half = 1;
    aq.oscale[0] = C2; aq.oscale[1] = 1.f; aq.oscale[2] = 1.f;
    gemm_mma_kernel<<<dim3(DD / 128, MM / 128, 3), 256, GEMM_SMEM>>>(aq);

    // 3) tensor-core flash attention
    flash_tc_kernel<<<dim3(SS / 128, BB * HH), 256, FLASH_SMEM>>>(qh, kh, vh, oh);

    // 4) output projection (fp32 out)
    GemmArgs ao{};
    ao.Ah = oh;
    ao.Wh[0] = wh + (size_t)3 * DD * DD;
    ao.Wh[1] = ao.Wh[0]; ao.Wh[2] = ao.Wh[0];
    ao.Cf = out;
    ao.rc = rc; ao.rs = rs; ao.nz_rope = 0; ao.out_half = 0;
    ao.oscale[0] = 1.f; ao.oscale[1] = 1.f; ao.oscale[2] = 1.f;
    gemm_mma_kernel<<<dim3(DD / 128, MM / 128, 1), 256, GEMM_SMEM>>>(ao);
}